// round 8
// baseline (speedup 1.0000x reference)
#include <cuda_runtime.h>
#include <cstdint>

// Problem constants:
// B=8, H=W=128, DIM=512, NH=8, HD=64, WIN=8x8 (N=64 tok/window), SHIFT=(4,4)
// windows: 2048 ; rows M = 131072

// Scratch (device globals = sanctioned scratch)
__device__ float g_qkv[3u * 2048u * 8u * 64u * 64u];  // [part][win][head][t][d]; q,k pre-RoPE'd
__device__ float g_o  [131072u * 512u];               // [m][h*64+d] (tf32-rounded)
__device__ float g_wq [1536u * 512u];                 // rounded qkv_w
__device__ float g_wp [512u * 512u];                  // rounded proj_w

// ---------------------------------------------------------------------------
// helpers
// ---------------------------------------------------------------------------
__device__ __forceinline__ uint32_t f2tf32(float f) {
    uint32_t u;
    asm("cvt.rna.tf32.f32 %0, %1;" : "=r"(u) : "f"(f));
    return u;
}
__device__ __forceinline__ void cp16(uint32_t smem, const void* gmem) {
    asm volatile("cp.async.cg.shared.global [%0], [%1], 16;\n" :: "r"(smem), "l"(gmem));
}
__device__ __forceinline__ void mma_tf32(float* c, const uint32_t* a, const uint32_t* b) {
    asm volatile(
        "mma.sync.aligned.m16n8k8.row.col.f32.tf32.tf32.f32 "
        "{%0,%1,%2,%3}, {%4,%5,%6,%7}, {%8,%9}, {%0,%1,%2,%3};"
        : "+f"(c[0]), "+f"(c[1]), "+f"(c[2]), "+f"(c[3])
        : "r"(a[0]), "r"(a[1]), "r"(a[2]), "r"(a[3]), "r"(b[0]), "r"(b[1]));
}

#define SSTRIDE 36                     // 32 floats + 4 pad, conflict-free frags
#define STAGE_F (128 * SSTRIDE * 2)    // floats per stage (A + B) = 9216
#define SMEM_BYTES (3 * STAGE_F * 4)   // 3 stages = 110592 B -> 2 CTAs/SM
#define L2T16 0.8304820237218406f      // log2(10000)/16

// ---------------------------------------------------------------------------
// Kernel 0: prep — round qkv_w / proj_w to tf32 bits.
// ---------------------------------------------------------------------------
__global__ __launch_bounds__(128) void k_prep_w(const float* __restrict__ qkv_w,
                                                const float* __restrict__ proj_w)
{
    const int w   = blockIdx.x;          // 0..2047
    const int tid = threadIdx.x;
    const float* src;
    float* dst;
    if (w < 1536) { src = qkv_w + (size_t)w * 512;           dst = g_wq + (size_t)w * 512; }
    else          { src = proj_w + (size_t)(w - 1536) * 512; dst = g_wp + (size_t)(w - 1536) * 512; }

    float4 v = ((const float4*)src)[tid];
    uint4 u;
    u.x = f2tf32(v.x); u.y = f2tf32(v.y); u.z = f2tf32(v.z); u.w = f2tf32(v.w);
    ((uint4*)dst)[tid] = u;
}

// ---------------------------------------------------------------------------
// Kernel 1: QKV GEMM (tf32) + fused gather on A + fused RoPE/scale epilogue.
//   M=131072 K=512 N=1536. 512 threads, 16 warps (4M x 4N), warp tile 32x32.
//   3-stage cp.async, 1 barrier/ktile, 2 CTAs/SM -> 8 warps/SMSP.
// ---------------------------------------------------------------------------
__global__ __launch_bounds__(512, 2) void k_qkv_gemm(const float* __restrict__ x,
                                                     const float* __restrict__ bias)
{
    extern __shared__ float sm[];
    __shared__ int rowOff[128];

    const int tid   = threadIdx.x;
    const int nTile = blockIdx.x;       // fastest -> A-tile L2 reuse
    const int mTile = blockIdx.y;

    if (tid < 128) {
        int m   = mTile * 128 + tid;
        int win = m >> 6, t = m & 63;
        int b   = win >> 8;
        int wh  = (win >> 4) & 15;
        int ww  = win & 15;
        int i   = t >> 3, j = t & 7;
        int r   = (wh * 8 + i + 4) & 127;     // roll(-4) gather
        int c   = (ww * 8 + j + 4) & 127;
        rowOff[tid] = ((((b << 7) | r) << 7) | c) << 9;   // *512 elements
    }
    __syncthreads();

    const int warpId = tid >> 5, lane = tid & 31;
    const int warpM  = warpId & 3;       // 0..3  (32-row strips)
    const int warpN  = warpId >> 2;      // 0..3  (32-col strips)
    const int rV     = lane >> 2, cq = lane & 3;

    float acc[2][4][4];
#pragma unroll
    for (int mi = 0; mi < 2; mi++)
#pragma unroll
        for (int ni = 0; ni < 4; ni++)
#pragma unroll
            for (int e = 0; e < 4; e++) acc[mi][ni][e] = 0.f;

    auto loadStage = [&](int s, int k0) {
        float* As = sm + s * STAGE_F;
        float* Bs = As + 128 * SSTRIDE;
#pragma unroll
        for (int it = 0; it < 2; it++) {
            int ch = tid + it * 512;          // 0..1023
            int row = ch >> 3, ci = ch & 7;
            uint32_t sa = (uint32_t)__cvta_generic_to_shared(As + row * SSTRIDE + ci * 4);
            cp16(sa, x + rowOff[row] + k0 + ci * 4);
            uint32_t sb = (uint32_t)__cvta_generic_to_shared(Bs + row * SSTRIDE + ci * 4);
            cp16(sb, g_wq + (size_t)(nTile * 128 + row) * 512 + k0 + ci * 4);
        }
    };

    loadStage(0, 0);
    asm volatile("cp.async.commit_group;\n");
    loadStage(1, 32);
    asm volatile("cp.async.commit_group;\n");
    asm volatile("cp.async.wait_group 1;\n");
    __syncthreads();

    int ldS = 2, cpS = 0;

    for (int kt = 0; kt < 16; kt++) {
        if (kt + 2 < 16) {
            loadStage(ldS, (kt + 2) * 32);
            asm volatile("cp.async.commit_group;\n");
            if (++ldS == 3) ldS = 0;
        }

        const float*    As = sm + cpS * STAGE_F;
        const uint32_t* Bs = (const uint32_t*)(As + 128 * SSTRIDE);
#pragma unroll
        for (int ks = 0; ks < 4; ks++) {
            uint32_t af[2][4];
#pragma unroll
            for (int mi = 0; mi < 2; mi++) {
                const float* ap = As + (warpM * 32 + mi * 16 + rV) * SSTRIDE + ks * 8 + cq;
                af[mi][0] = f2tf32(ap[0]);
                af[mi][1] = f2tf32(ap[8 * SSTRIDE]);
                af[mi][2] = f2tf32(ap[4]);
                af[mi][3] = f2tf32(ap[8 * SSTRIDE + 4]);
            }
#pragma unroll
            for (int ni = 0; ni < 4; ni++) {
                const uint32_t* bp = Bs + (warpN * 32 + ni * 8 + rV) * SSTRIDE + ks * 8 + cq;
                uint32_t bf[2] = { bp[0], bp[4] };
                mma_tf32(acc[0][ni], af[0], bf);
                mma_tf32(acc[1][ni], af[1], bf);
            }
        }
        if (++cpS == 3) cpS = 0;

        if (kt < 15) {
            if (kt + 2 < 16) asm volatile("cp.async.wait_group 1;\n");
            else             asm volatile("cp.async.wait_group 0;\n");
            __syncthreads();
        }
    }

    // ---- Epilogue: bias, then fused RoPE (+0.125 scale on Q), then scatter ----
    const int nb    = nTile * 128 + warpN * 32;   // 32-aligned; part/h/dHalf warp-uniform
    const int part  = nb >> 9;
    const int h     = (nb >> 6) & 7;
    const int dHalf = (nb >> 5) & 1;              // 0: d in [0,32), 1: [32,64)

    // bias first (reference: qkv = xw@W + b, THEN rope)
#pragma unroll
    for (int ni = 0; ni < 4; ni++) {
        int n = nb + ni * 8 + 2 * cq;
        float b0 = bias[n], b1 = bias[n + 1];
#pragma unroll
        for (int mi = 0; mi < 2; mi++) {
            acc[mi][ni][0] += b0; acc[mi][ni][1] += b1;
            acc[mi][ni][2] += b0; acc[mi][ni][3] += b1;
        }
    }

    if (part < 2) {
        const float scale = (part == 0) ? 0.125f : 1.0f;
        // inv factors: pair base e = ni*8 + 2cq + j, ni in {0,1}
        float inv[2][2];
#pragma unroll
        for (int ni = 0; ni < 2; ni++)
#pragma unroll
            for (int j = 0; j < 2; j++)
                inv[ni][j] = exp2f(-(float)(ni * 8 + 2 * cq + j) * L2T16);

#pragma unroll
        for (int mi = 0; mi < 2; mi++) {
#pragma unroll
            for (int rr = 0; rr < 2; rr++) {
                int t = (mTile * 128 + warpM * 32 + mi * 16 + rV + rr * 8) & 63;
                float pos = dHalf ? (float)(t & 7) : (float)(t >> 3);
#pragma unroll
                for (int ni = 0; ni < 2; ni++) {
#pragma unroll
                    for (int j = 0; j < 2; j++) {
                        float ang = pos * inv[ni][j];
                        float sv, cv;
                        __sincosf(ang, &sv, &cv);
                        float a = acc[mi][ni][rr * 2 + j];
                        float b = acc[mi][ni + 2][rr * 2 + j];
                        acc[mi][ni][rr * 2 + j]     = (a * cv - b * sv) * scale;
                        acc[mi][ni + 2][rr * 2 + j] = (b * cv + a * sv) * scale;
                    }
                }
            }
        }
    }

    // scatter into g_qkv[part][win][h][t][d]
#pragma unroll
    for (int ni = 0; ni < 4; ni++) {
        int d0 = (nb + ni * 8 + 2 * cq) & 63;
#pragma unroll
        for (int mi = 0; mi < 2; mi++) {
#pragma unroll
            for (int rr = 0; rr < 2; rr++) {
                int m   = mTile * 128 + warpM * 32 + mi * 16 + rV + rr * 8;
                int win = m >> 6, t = m & 63;
                size_t idx = ((((size_t)part * 2048 + win) * 8 + h) * 64 + t) * 64 + d0;
                *(float2*)(g_qkv + idx) =
                    make_float2(acc[mi][ni][rr * 2 + 0], acc[mi][ni][rr * 2 + 1]);
            }
        }
    }
}

// ---------------------------------------------------------------------------
// Kernel 2: per (window, head) attention (tf32 mma). Q,K arrive pre-RoPE'd
// and pre-scaled — no transform pass here.
// ---------------------------------------------------------------------------
#define AST 68

__global__ __launch_bounds__(128) void k_attn_mma()
{
    __shared__ float Qb[64 * AST];
    __shared__ float Kb[64 * AST];

    const int tid  = threadIdx.x;
    const int warp = tid >> 5;
    const int lane = tid & 31;
    const int r    = lane >> 2;
    const int c    = lane & 3;
    const int m0   = warp * 16;

    const int win = blockIdx.x >> 3;
    const int h   = blockIdx.x & 7;

    const size_t qbase = ((size_t)win * 8 + h) * 4096;
    const float4* qg = (const float4*)(g_qkv + qbase);
    const float4* kg = (const float4*)(g_qkv + (size_t)2048 * 8 * 4096 + qbase);
    const float4* vg = (const float4*)(g_qkv + (size_t)2 * 2048 * 8 * 4096 + qbase);

#pragma unroll
    for (int it = 0; it < 8; it++) {
        int e4 = tid + it * 128;
        int t  = e4 >> 4;
        int d4 = (e4 & 15) * 4;
        *(float4*)(Qb + t * AST + d4) = qg[e4];
        *(float4*)(Kb + t * AST + d4) = kg[e4];
    }
    __syncthreads();

    // ---- S = Q K^T ----
    uint32_t areg[8][4];
#pragma unroll
    for (int ks = 0; ks < 8; ks++) {
        const float* ap = Qb + (m0 + r) * AST + ks * 8 + c;
        areg[ks][0] = f2tf32(ap[0]);
        areg[ks][1] = f2tf32(ap[8 * AST]);
        areg[ks][2] = f2tf32(ap[4]);
        areg[ks][3] = f2tf32(ap[8 * AST + 4]);
    }

    float sacc[8][4];
#pragma unroll
    for (int ni = 0; ni < 8; ni++)
#pragma unroll
        for (int e = 0; e < 4; e++) sacc[ni][e] = 0.f;

#pragma unroll
    for (int ni = 0; ni < 8; ni++) {
        const float* bbase = Kb + (ni * 8 + r) * AST + c;
#pragma unroll
        for (int ks = 0; ks < 8; ks++) {
            uint32_t bf[2];
            bf[0] = f2tf32(bbase[ks * 8]);
            bf[1] = f2tf32(bbase[ks * 8 + 4]);
            mma_tf32(sacc[ni], areg[ks], bf);
        }
    }
    __syncthreads();   // all warps done with Kb -> reuse for V

#pragma unroll
    for (int it = 0; it < 8; it++) {
        int e4 = tid + it * 128;
        int t  = e4 >> 4;
        int d4 = (e4 & 15) * 4;
        *(float4*)(Kb + t * AST + d4) = vg[e4];
    }

    // ---- mask + softmax in registers ----
    const bool maskOn = (((win >> 4) & 15) == 15);
    const bool warpLo = (warp < 2);

    float mx1 = -1e30f, mx2 = -1e30f;
#pragma unroll
    for (int ni = 0; ni < 8; ni++) {
        float msub = (maskOn && ((ni < 4) != warpLo)) ? 100.f : 0.f;
        sacc[ni][0] -= msub; sacc[ni][1] -= msub;
        sacc[ni][2] -= msub; sacc[ni][3] -= msub;
        mx1 = fmaxf(mx1, fmaxf(sacc[ni][0], sacc[ni][1]));
        mx2 = fmaxf(mx2, fmaxf(sacc[ni][2], sacc[ni][3]));
    }
    mx1 = fmaxf(mx1, __shfl_xor_sync(0xffffffffu, mx1, 1));
    mx1 = fmaxf(mx1, __shfl_xor_sync(0xffffffffu, mx1, 2));
    mx2 = fmaxf(mx2, __shfl_xor_sync(0xffffffffu, mx2, 1));
    mx2 = fmaxf(mx2, __shfl_xor_sync(0xffffffffu, mx2, 2));

    float s1 = 0.f, s2 = 0.f;
#pragma unroll
    for (int ni = 0; ni < 8; ni++) {
        sacc[ni][0] = __expf(sacc[ni][0] - mx1);
        sacc[ni][1] = __expf(sacc[ni][1] - mx1);
        sacc[ni][2] = __expf(sacc[ni][2] - mx2);
        sacc[ni][3] = __expf(sacc[ni][3] - mx2);
        s1 += sacc[ni][0] + sacc[ni][1];
        s2 += sacc[ni][2] + sacc[ni][3];
    }
    s1 += __shfl_xor_sync(0xffffffffu, s1, 1);
    s1 += __shfl_xor_sync(0xffffffffu, s1, 2);
    s2 += __shfl_xor_sync(0xffffffffu, s2, 1);
    s2 += __shfl_xor_sync(0xffffffffu, s2, 2);
    const float i1 = 1.f / s1, i2 = 1.f / s2;

#pragma unroll
    for (int ni = 0; ni < 8; ni++) {
        *(float2*)(Qb + (m0 + r) * AST + ni * 8 + 2 * c) =
            make_float2(sacc[ni][0] * i1, sacc[ni][1] * i1);
        *(float2*)(Qb + (m0 + r + 8) * AST + ni * 8 + 2 * c) =
            make_float2(sacc[ni][2] * i2, sacc[ni][3] * i2);
    }
    __syncthreads();

    // ---- O = P V ----
    uint32_t preg[8][4];
#pragma unroll
    for (int ks = 0; ks < 8; ks++) {
        const float* pp = Qb + (m0 + r) * AST + ks * 8 + c;
        preg[ks][0] = f2tf32(pp[0]);
        preg[ks][1] = f2tf32(pp[8 * AST]);
        preg[ks][2] = f2tf32(pp[4]);
        preg[ks][3] = f2tf32(pp[8 * AST + 4]);
    }

    float oacc[8][4];
#pragma unroll
    for (int ni = 0; ni < 8; ni++)
#pragma unroll
        for (int e = 0; e < 4; e++) oacc[ni][e] = 0.f;

#pragma unroll
    for (int ni = 0; ni < 8; ni++) {
        const float* vb = Kb + c * AST + ni * 8 + r;
#pragma unroll
        for (int ks = 0; ks < 8; ks++) {
            uint32_t bf[2];
            bf[0] = f2tf32(vb[ks * 8 * AST]);
            bf[1] = f2tf32(vb[(ks * 8 + 4) * AST]);
            mma_tf32(oacc[ni], preg[ks], bf);
        }
    }

    uint32_t* go32 = (uint32_t*)g_o;
    const size_t mrow1 = (size_t)win * 64 + m0 + r;
    const size_t mrow2 = mrow1 + 8;
#pragma unroll
    for (int ni = 0; ni < 8; ni++) {
        int d0 = h * 64 + ni * 8 + 2 * c;
        uint2 v1 = make_uint2(f2tf32(oacc[ni][0]), f2tf32(oacc[ni][1]));
        uint2 v2 = make_uint2(f2tf32(oacc[ni][2]), f2tf32(oacc[ni][3]));
        *(uint2*)(go32 + mrow1 * 512 + d0) = v1;
        *(uint2*)(go32 + mrow2 * 512 + d0) = v2;
    }
}

// ---------------------------------------------------------------------------
// Kernel 3: proj GEMM (tf32, pre-rounded) + bias + unpartition/roll scatter.
// 512 threads, 16 warps (4x4), warp tile 32x32, 3-stage / 1-barrier.
// ---------------------------------------------------------------------------
__global__ __launch_bounds__(512, 2) void k_proj_gemm(const float* __restrict__ bias,
                                                      float* __restrict__ out)
{
    extern __shared__ float sm[];

    const int tid   = threadIdx.x;
    const int nTile = blockIdx.x;
    const int mTile = blockIdx.y;

    const int warpId = tid >> 5, lane = tid & 31;
    const int warpM  = warpId & 3;
    const int warpN  = warpId >> 2;
    const int n0     = nTile * 128;
    const int rV     = lane >> 2, cq = lane & 3;

    float acc[2][4][4];
#pragma unroll
    for (int mi = 0; mi < 2; mi++)
#pragma unroll
        for (int ni = 0; ni < 4; ni++)
#pragma unroll
            for (int e = 0; e < 4; e++) acc[mi][ni][e] = 0.f;

    auto loadStage = [&](int s, int k0) {
        float* As = sm + s * STAGE_F;
        float* Bs = As + 128 * SSTRIDE;
#pragma unroll
        for (int it = 0; it < 2; it++) {
            int ch = tid + it * 512;
            int row = ch >> 3, ci = ch & 7;
            uint32_t sa = (uint32_t)__cvta_generic_to_shared(As + row * SSTRIDE + ci * 4);
            cp16(sa, g_o + (size_t)(mTile * 128 + row) * 512 + k0 + ci * 4);
            uint32_t sb = (uint32_t)__cvta_generic_to_shared(Bs + row * SSTRIDE + ci * 4);
            cp16(sb, g_wp + (size_t)(n0 + row) * 512 + k0 + ci * 4);
        }
    };

    loadStage(0, 0);
    asm volatile("cp.async.commit_group;\n");
    loadStage(1, 32);
    asm volatile("cp.async.commit_group;\n");
    asm volatile("cp.async.wait_group 1;\n");
    __syncthreads();

    int ldS = 2, cpS = 0;

    for (int kt = 0; kt < 16; kt++) {
        if (kt + 2 < 16) {
            loadStage(ldS, (kt + 2) * 32);
            asm volatile("cp.async.commit_group;\n");
            if (++ldS == 3) ldS = 0;
        }

        const uint32_t* As = (const uint32_t*)(sm + cpS * STAGE_F);
        const uint32_t* Bs = As + 128 * SSTRIDE;
#pragma unroll
        for (int ks = 0; ks < 4; ks++) {
            uint32_t af[2][4];
#pragma unroll
            for (int mi = 0; mi < 2; mi++) {
                const uint32_t* ap = As + (warpM * 32 + mi * 16 + rV) * SSTRIDE + ks * 8 + cq;
                af[mi][0] = ap[0];
                af[mi][1] = ap[8 * SSTRIDE];
                af[mi][2] = ap[4];
                af[mi][3] = ap[8 * SSTRIDE + 4];
            }
#pragma unroll
            for (int ni = 0; ni < 4; ni++) {
                const uint32_t* bp = Bs + (warpN * 32 + ni * 8 + rV) * SSTRIDE + ks * 8 + cq;
                uint32_t bf[2] = { bp[0], bp[4] };
                mma_tf32(acc[0][ni], af[0], bf);
                mma_tf32(acc[1][ni], af[1], bf);
            }
        }
        if (++cpS == 3) cpS = 0;

        if (kt < 15) {
            if (kt + 2 < 16) asm volatile("cp.async.wait_group 1;\n");
            else             asm volatile("cp.async.wait_group 0;\n");
            __syncthreads();
        }
    }

#pragma unroll
    for (int ni = 0; ni < 4; ni++) {
        int n  = n0 + warpN * 32 + ni * 8 + 2 * cq;
        float b0 = bias[n], b1 = bias[n + 1];
#pragma unroll
        for (int mi = 0; mi < 2; mi++) {
#pragma unroll
            for (int rr2 = 0; rr2 < 2; rr2++) {
                int m   = mTile * 128 + warpM * 32 + mi * 16 + rV + rr2 * 8;
                int win = m >> 6, t = m & 63;
                int b   = win >> 8;
                int wh  = (win >> 4) & 15;
                int ww  = win & 15;
                int ii  = t >> 3, jj = t & 7;
                int rO  = (wh * 8 + ii + 4) & 127;
                int cO  = (ww * 8 + jj + 4) & 127;
                size_t off = ((((size_t)b << 7) | rO) << 7 | cO) << 9;
                float2 v = make_float2(acc[mi][ni][rr2 * 2 + 0] + b0,
                                       acc[mi][ni][rr2 * 2 + 1] + b1);
                *(float2*)(out + off + n) = v;
            }
        }
    }
}

// ---------------------------------------------------------------------------
extern "C" void kernel_launch(void* const* d_in, const int* in_sizes, int n_in,
                              void* d_out, int out_size)
{
    const float* x      = (const float*)d_in[0];
    const float* qkv_w  = (const float*)d_in[1];
    const float* qkv_b  = (const float*)d_in[2];
    const float* proj_w = (const float*)d_in[3];
    const float* proj_b = (const float*)d_in[4];
    float* out = (float*)d_out;

    cudaFuncSetAttribute(k_qkv_gemm,  cudaFuncAttributeMaxDynamicSharedMemorySize, SMEM_BYTES);
    cudaFuncSetAttribute(k_proj_gemm, cudaFuncAttributeMaxDynamicSharedMemorySize, SMEM_BYTES);

    k_prep_w<<<2048, 128>>>(qkv_w, proj_w);
    k_qkv_gemm<<<dim3(12, 1024), 512, SMEM_BYTES>>>(x, qkv_b);
    k_attn_mma<<<2048 * 8, 128>>>();
    k_proj_gemm<<<dim3(4, 1024), 512, SMEM_BYTES>>>(proj_b, out);
}

// round 9
// speedup vs baseline: 1.4674x; 1.4674x over previous
#include <cuda_runtime.h>
#include <cuda_fp16.h>
#include <cstdint>

// Problem constants:
// B=8, H=W=128, DIM=512, NH=8, HD=64, WIN=8x8 (N=64 tok/window), SHIFT=(4,4)
// windows: 2048 ; rows M = 131072

// Scratch (device globals = sanctioned scratch)
__device__ float  g_qkv[3u * 2048u * 8u * 64u * 64u]; // [part][win][head][t][d] fp32
__device__ __half g_xh [131072u * 512u];              // gathered x, fp16
__device__ __half g_oh [131072u * 512u];              // attention out, fp16
__device__ __half g_wqh[1536u * 512u];                // qkv_w fp16
__device__ __half g_wph[512u * 512u];                 // proj_w fp16

// ---------------------------------------------------------------------------
// helpers
// ---------------------------------------------------------------------------
__device__ __forceinline__ uint32_t f2tf32(float f) {
    uint32_t u;
    asm("cvt.rna.tf32.f32 %0, %1;" : "=r"(u) : "f"(f));
    return u;
}
__device__ __forceinline__ void cp16(uint32_t smem, const void* gmem) {
    asm volatile("cp.async.cg.shared.global [%0], [%1], 16;\n" :: "r"(smem), "l"(gmem));
}
__device__ __forceinline__ void mma_tf32(float* c, const uint32_t* a, const uint32_t* b) {
    asm volatile(
        "mma.sync.aligned.m16n8k8.row.col.f32.tf32.tf32.f32 "
        "{%0,%1,%2,%3}, {%4,%5,%6,%7}, {%8,%9}, {%0,%1,%2,%3};"
        : "+f"(c[0]), "+f"(c[1]), "+f"(c[2]), "+f"(c[3])
        : "r"(a[0]), "r"(a[1]), "r"(a[2]), "r"(a[3]), "r"(b[0]), "r"(b[1]));
}
__device__ __forceinline__ void mma_f16(float* c, const uint32_t* a, const uint32_t* b) {
    asm volatile(
        "mma.sync.aligned.m16n8k16.row.col.f32.f16.f16.f32 "
        "{%0,%1,%2,%3}, {%4,%5,%6,%7}, {%8,%9}, {%0,%1,%2,%3};"
        : "+f"(c[0]), "+f"(c[1]), "+f"(c[2]), "+f"(c[3])
        : "r"(a[0]), "r"(a[1]), "r"(a[2]), "r"(a[3]), "r"(b[0]), "r"(b[1]));
}
// pack (lo=v0, hi=v1) into f16x2 word
__device__ __forceinline__ uint32_t pack_h2(float v0, float v1) {
    uint32_t p;
    asm("cvt.rn.f16x2.f32 %0, %1, %2;" : "=r"(p) : "f"(v1), "f"(v0));
    return p;
}

// fp16 GEMM smem geometry: rows of 32 halves padded to 40 (80 B) -> LDS.32
// fragment loads conflict-free (bank = (20*g + t) mod 32, all distinct).
#define HSTR32 20                       // row stride in 32-bit words
#define STAGE_W (256 * HSTR32)          // words per stage (A 128 rows + B 128 rows)
#define SMEM_BYTES (3 * STAGE_W * 4)    // 61440 B -> 2 CTAs/SM

// ---------------------------------------------------------------------------
// Kernel 0: prep — gather x (roll+partition) -> g_xh (fp16); weights -> fp16.
// ---------------------------------------------------------------------------
__global__ __launch_bounds__(128) void k_prep(const float* __restrict__ x,
                                              const float* __restrict__ qkv_w,
                                              const float* __restrict__ proj_w)
{
    const int bid = blockIdx.x;
    const int tid = threadIdx.x;

    const float* src;
    __half* dst;
    if (bid < 131072) {
        int m   = bid;
        int win = m >> 6, t = m & 63;
        int b   = win >> 8;
        int wh  = (win >> 4) & 15;
        int ww  = win & 15;
        int i   = t >> 3, j = t & 7;
        int r   = (wh * 8 + i + 4) & 127;     // roll(-4) gather
        int c   = (ww * 8 + j + 4) & 127;
        src = x + ((size_t)((((b << 7) | r) << 7) | c) << 9);
        dst = g_xh + (size_t)m * 512;
    } else {
        int w = bid - 131072;                  // 0..2047
        if (w < 1536) { src = qkv_w + (size_t)w * 512;           dst = g_wqh + (size_t)w * 512; }
        else          { src = proj_w + (size_t)(w - 1536) * 512; dst = g_wph + (size_t)(w - 1536) * 512; }
    }

    float4 v = ((const float4*)src)[tid];
    uint2 o;
    o.x = pack_h2(v.x, v.y);
    o.y = pack_h2(v.z, v.w);
    ((uint2*)dst)[tid] = o;
}

// ---------------------------------------------------------------------------
// fp16 GEMM core (shared by QKV and proj): BM=BN=128, BK=32, K=512,
// 256 threads, 8 warps (4M x 2N), warp tile 32x64, m16n8k16,
// 3-stage cp.async, 1 barrier per ktile. Accumulators fp32.
// ---------------------------------------------------------------------------
#define GEMM_MAIN(APTR, BPTR)                                                  \
    auto loadStage = [&](int s, int k0) {                                      \
        uint32_t ab = smemBase + s * (STAGE_W * 4);                            \
        uint32_t bb = ab + 128 * 80;                                           \
        _Pragma("unroll")                                                      \
        for (int it = 0; it < 2; it++) {                                       \
            int ch = tid + it * 256;          /* 0..511 */                     \
            int row = ch >> 2, ci = ch & 3;   /* 16B chunks, 4 per row */      \
            cp16(ab + row * 80 + ci * 16, APTR + (size_t)row * 512 + k0 + ci * 8); \
            cp16(bb + row * 80 + ci * 16, BPTR + (size_t)row * 512 + k0 + ci * 8); \
        }                                                                      \
    };                                                                         \
    loadStage(0, 0);                                                           \
    asm volatile("cp.async.commit_group;\n");                                  \
    loadStage(1, 32);                                                          \
    asm volatile("cp.async.commit_group;\n");                                  \
    asm volatile("cp.async.wait_group 1;\n");                                  \
    __syncthreads();                                                           \
    int ldS = 2, cpS = 0;                                                      \
    for (int kt = 0; kt < 16; kt++) {                                          \
        if (kt + 2 < 16) {                                                     \
            loadStage(ldS, (kt + 2) * 32);                                     \
            asm volatile("cp.async.commit_group;\n");                          \
            if (++ldS == 3) ldS = 0;                                           \
        }                                                                      \
        const uint32_t* As = sm32 + cpS * STAGE_W;                             \
        const uint32_t* Bs = As + 128 * HSTR32;                                \
        _Pragma("unroll")                                                      \
        for (int ks = 0; ks < 2; ks++) {                                       \
            uint32_t af[2][4];                                                 \
            _Pragma("unroll")                                                  \
            for (int mi = 0; mi < 2; mi++) {                                   \
                const uint32_t* ap = As + (warpM * 32 + mi * 16 + g) * HSTR32 + ks * 8 + t4; \
                af[mi][0] = ap[0];                                             \
                af[mi][1] = ap[8 * HSTR32];                                    \
                af[mi][2] = ap[4];                                             \
                af[mi][3] = ap[8 * HSTR32 + 4];                                \
            }                                                                  \
            _Pragma("unroll")                                                  \
            for (int ni = 0; ni < 8; ni++) {                                   \
                const uint32_t* bp = Bs + (warpN * 64 + ni * 8 + g) * HSTR32 + ks * 8 + t4; \
                uint32_t bf[2] = { bp[0], bp[4] };                             \
                mma_f16(acc[0][ni], af[0], bf);                                \
                mma_f16(acc[1][ni], af[1], bf);                                \
            }                                                                  \
        }                                                                      \
        if (++cpS == 3) cpS = 0;                                               \
        if (kt < 15) {                                                         \
            if (kt + 2 < 16) asm volatile("cp.async.wait_group 1;\n");         \
            else             asm volatile("cp.async.wait_group 0;\n");         \
            __syncthreads();                                                   \
        }                                                                      \
    }

// ---------------------------------------------------------------------------
// Kernel 1: QKV GEMM (fp16) + bias + scatter into g_qkv (fp32).
//   M=131072 K=512 N=1536
// ---------------------------------------------------------------------------
__global__ __launch_bounds__(256, 2) void k_qkv_gemm(const float* __restrict__ bias)
{
    extern __shared__ uint32_t sm32[];
    const uint32_t smemBase = (uint32_t)__cvta_generic_to_shared(sm32);

    const int tid   = threadIdx.x;
    const int nTile = blockIdx.x;
    const int mTile = blockIdx.y;

    const int warpId = tid >> 5, lane = tid & 31;
    const int warpM  = warpId & 3;
    const int warpN  = warpId >> 2;
    const int n0     = nTile * 128;
    const int g      = lane >> 2, t4 = lane & 3;

    float acc[2][8][4];
#pragma unroll
    for (int mi = 0; mi < 2; mi++)
#pragma unroll
        for (int ni = 0; ni < 8; ni++)
#pragma unroll
            for (int e = 0; e < 4; e++) acc[mi][ni][e] = 0.f;

    const __half* Ag = g_xh + (size_t)(mTile * 128) * 512;
    const __half* Bg = g_wqh + (size_t)n0 * 512;
    GEMM_MAIN(Ag, Bg)

    // Epilogue: bias + scatter into g_qkv[part][win][h][t][d]
#pragma unroll
    for (int ni = 0; ni < 8; ni++) {
        int n  = n0 + warpN * 64 + ni * 8 + 2 * t4;
        float b0 = bias[n], b1 = bias[n + 1];
        int part = n >> 9;
        int h    = (n >> 6) & 7;
        int d0   = n & 63;
#pragma unroll
        for (int mi = 0; mi < 2; mi++) {
#pragma unroll
            for (int rr = 0; rr < 2; rr++) {
                int m   = mTile * 128 + warpM * 32 + mi * 16 + g + rr * 8;
                int win = m >> 6, tt = m & 63;
                size_t idx = ((((size_t)part * 2048 + win) * 8 + h) * 64 + tt) * 64 + d0;
                float2 v = make_float2(acc[mi][ni][rr * 2 + 0] + b0,
                                       acc[mi][ni][rr * 2 + 1] + b1);
                *(float2*)(g_qkv + idx) = v;
            }
        }
    }
}

// ---------------------------------------------------------------------------
// Kernel 2: per (window, head) attention (tf32 mma, fp32 smem) — R7 design.
// RoPE inside; output stored as fp16 into g_oh for the fp16 proj GEMM.
// ---------------------------------------------------------------------------
#define AST 68

__global__ __launch_bounds__(128) void k_attn_mma()
{
    __shared__ float Qb[64 * AST];
    __shared__ float Kb[64 * AST];

    const int tid  = threadIdx.x;
    const int warp = tid >> 5;
    const int lane = tid & 31;
    const int r    = lane >> 2;
    const int c    = lane & 3;
    const int m0   = warp * 16;

    const int win = blockIdx.x >> 3;
    const int h   = blockIdx.x & 7;

    const size_t qbase = ((size_t)win * 8 + h) * 4096;
    const float4* qg = (const float4*)(g_qkv + qbase);
    const float4* kg = (const float4*)(g_qkv + (size_t)2048 * 8 * 4096 + qbase);
    const float4* vg = (const float4*)(g_qkv + (size_t)2 * 2048 * 8 * 4096 + qbase);

#pragma unroll
    for (int it = 0; it < 8; it++) {
        int e4 = tid + it * 128;
        int t  = e4 >> 4;
        int d4 = (e4 & 15) * 4;
        *(float4*)(Qb + t * AST + d4) = qg[e4];
        *(float4*)(Kb + t * AST + d4) = kg[e4];
    }
    __syncthreads();

    const float L2_10000 = 13.287712379549449f;
#pragma unroll
    for (int it = 0; it < 16; it++) {
        int p = tid + it * 128;
        int t = p >> 5, q = p & 31;
        int db = (q < 16) ? q : (q + 16);
        int e  = db & 15;
        float pos = (db < 32) ? (float)(t >> 3) : (float)(t & 7);
        float inv = exp2f(-(float)e * (L2_10000 / 16.f));
        float ang = pos * inv;
        float cv = cosf(ang), sv = sinf(ang);

        float a = Qb[t * AST + db], b = Qb[t * AST + db + 16];
        Qb[t * AST + db]      = (a * cv - b * sv) * 0.125f;
        Qb[t * AST + db + 16] = (b * cv + a * sv) * 0.125f;

        a = Kb[t * AST + db]; b = Kb[t * AST + db + 16];
        Kb[t * AST + db]      = a * cv - b * sv;
        Kb[t * AST + db + 16] = b * cv + a * sv;
    }
    __syncthreads();

    uint32_t areg[8][4];
#pragma unroll
    for (int ks = 0; ks < 8; ks++) {
        const float* ap = Qb + (m0 + r) * AST + ks * 8 + c;
        areg[ks][0] = f2tf32(ap[0]);
        areg[ks][1] = f2tf32(ap[8 * AST]);
        areg[ks][2] = f2tf32(ap[4]);
        areg[ks][3] = f2tf32(ap[8 * AST + 4]);
    }

    float sacc[8][4];
#pragma unroll
    for (int ni = 0; ni < 8; ni++)
#pragma unroll
        for (int e = 0; e < 4; e++) sacc[ni][e] = 0.f;

#pragma unroll
    for (int ni = 0; ni < 8; ni++) {
        const float* bbase = Kb + (ni * 8 + r) * AST + c;
#pragma unroll
        for (int ks = 0; ks < 8; ks++) {
            uint32_t bf[2];
            bf[0] = f2tf32(bbase[ks * 8]);
            bf[1] = f2tf32(bbase[ks * 8 + 4]);
            mma_tf32(sacc[ni], areg[ks], bf);
        }
    }
    __syncthreads();

#pragma unroll
    for (int it = 0; it < 8; it++) {
        int e4 = tid + it * 128;
        int t  = e4 >> 4;
        int d4 = (e4 & 15) * 4;
        *(float4*)(Kb + t * AST + d4) = vg[e4];
    }

    const bool maskOn = (((win >> 4) & 15) == 15);
    const bool warpLo = (warp < 2);

    float mx1 = -1e30f, mx2 = -1e30f;
#pragma unroll
    for (int ni = 0; ni < 8; ni++) {
        float msub = (maskOn && ((ni < 4) != warpLo)) ? 100.f : 0.f;
        sacc[ni][0] -= msub; sacc[ni][1] -= msub;
        sacc[ni][2] -= msub; sacc[ni][3] -= msub;
        mx1 = fmaxf(mx1, fmaxf(sacc[ni][0], sacc[ni][1]));
        mx2 = fmaxf(mx2, fmaxf(sacc[ni][2], sacc[ni][3]));
    }
    mx1 = fmaxf(mx1, __shfl_xor_sync(0xffffffffu, mx1, 1));
    mx1 = fmaxf(mx1, __shfl_xor_sync(0xffffffffu, mx1, 2));
    mx2 = fmaxf(mx2, __shfl_xor_sync(0xffffffffu, mx2, 1));
    mx2 = fmaxf(mx2, __shfl_xor_sync(0xffffffffu, mx2, 2));

    float s1 = 0.f, s2 = 0.f;
#pragma unroll
    for (int ni = 0; ni < 8; ni++) {
        sacc[ni][0] = __expf(sacc[ni][0] - mx1);
        sacc[ni][1] = __expf(sacc[ni][1] - mx1);
        sacc[ni][2] = __expf(sacc[ni][2] - mx2);
        sacc[ni][3] = __expf(sacc[ni][3] - mx2);
        s1 += sacc[ni][0] + sacc[ni][1];
        s2 += sacc[ni][2] + sacc[ni][3];
    }
    s1 += __shfl_xor_sync(0xffffffffu, s1, 1);
    s1 += __shfl_xor_sync(0xffffffffu, s1, 2);
    s2 += __shfl_xor_sync(0xffffffffu, s2, 1);
    s2 += __shfl_xor_sync(0xffffffffu, s2, 2);
    const float i1 = 1.f / s1, i2 = 1.f / s2;

#pragma unroll
    for (int ni = 0; ni < 8; ni++) {
        *(float2*)(Qb + (m0 + r) * AST + ni * 8 + 2 * c) =
            make_float2(sacc[ni][0] * i1, sacc[ni][1] * i1);
        *(float2*)(Qb + (m0 + r + 8) * AST + ni * 8 + 2 * c) =
            make_float2(sacc[ni][2] * i2, sacc[ni][3] * i2);
    }
    __syncthreads();

    uint32_t preg[8][4];
#pragma unroll
    for (int ks = 0; ks < 8; ks++) {
        const float* pp = Qb + (m0 + r) * AST + ks * 8 + c;
        preg[ks][0] = f2tf32(pp[0]);
        preg[ks][1] = f2tf32(pp[8 * AST]);
        preg[ks][2] = f2tf32(pp[4]);
        preg[ks][3] = f2tf32(pp[8 * AST + 4]);
    }

    float oacc[8][4];
#pragma unroll
    for (int ni = 0; ni < 8; ni++)
#pragma unroll
        for (int e = 0; e < 4; e++) oacc[ni][e] = 0.f;

#pragma unroll
    for (int ni = 0; ni < 8; ni++) {
        const float* vb = Kb + c * AST + ni * 8 + r;
#pragma unroll
        for (int ks = 0; ks < 8; ks++) {
            uint32_t bf[2];
            bf[0] = f2tf32(vb[ks * 8 * AST]);
            bf[1] = f2tf32(vb[(ks * 8 + 4) * AST]);
            mma_tf32(oacc[ni], preg[ks], bf);
        }
    }

    // store O as fp16 into g_oh[m][h*64+d]
    uint32_t* goh = (uint32_t*)g_oh;           // 2 halves per word
    const size_t mrow1 = (size_t)win * 64 + m0 + r;
    const size_t mrow2 = mrow1 + 8;
#pragma unroll
    for (int ni = 0; ni < 8; ni++) {
        int d0 = h * 64 + ni * 8 + 2 * c;      // even -> word-aligned
        goh[(mrow1 * 512 + d0) >> 1] = pack_h2(oacc[ni][0], oacc[ni][1]);
        goh[(mrow2 * 512 + d0) >> 1] = pack_h2(oacc[ni][2], oacc[ni][3]);
    }
}

// ---------------------------------------------------------------------------
// Kernel 3: proj GEMM (fp16) + bias + unpartition/roll scatter.
//   M=131072 K=512 N=512
// ---------------------------------------------------------------------------
__global__ __launch_bounds__(256, 2) void k_proj_gemm(const float* __restrict__ bias,
                                                      float* __restrict__ out)
{
    extern __shared__ uint32_t sm32[];
    const uint32_t smemBase = (uint32_t)__cvta_generic_to_shared(sm32);

    const int tid   = threadIdx.x;
    const int nTile = blockIdx.x;
    const int mTile = blockIdx.y;

    const int warpId = tid >> 5, lane = tid & 31;
    const int warpM  = warpId & 3;
    const int warpN  = warpId >> 2;
    const int n0     = nTile * 128;
    const int g      = lane >> 2, t4 = lane & 3;

    float acc[2][8][4];
#pragma unroll
    for (int mi = 0; mi < 2; mi++)
#pragma unroll
        for (int ni = 0; ni < 8; ni++)
#pragma unroll
            for (int e = 0; e < 4; e++) acc[mi][ni][e] = 0.f;

    const __half* Ag = g_oh + (size_t)(mTile * 128) * 512;
    const __half* Bg = g_wph + (size_t)n0 * 512;
    GEMM_MAIN(Ag, Bg)

    // Epilogue: bias + unpartition/roll(+4) scatter
#pragma unroll
    for (int ni = 0; ni < 8; ni++) {
        int n  = n0 + warpN * 64 + ni * 8 + 2 * t4;
        float b0 = bias[n], b1 = bias[n + 1];
#pragma unroll
        for (int mi = 0; mi < 2; mi++) {
#pragma unroll
            for (int rr2 = 0; rr2 < 2; rr2++) {
                int m   = mTile * 128 + warpM * 32 + mi * 16 + g + rr2 * 8;
                int win = m >> 6, tt = m & 63;
                int b   = win >> 8;
                int wh  = (win >> 4) & 15;
                int ww  = win & 15;
                int ii  = tt >> 3, jj = tt & 7;
                int rO  = (wh * 8 + ii + 4) & 127;
                int cO  = (ww * 8 + jj + 4) & 127;
                size_t off = ((((size_t)b << 7) | rO) << 7 | cO) << 9;
                float2 v = make_float2(acc[mi][ni][rr2 * 2 + 0] + b0,
                                       acc[mi][ni][rr2 * 2 + 1] + b1);
                *(float2*)(out + off + n) = v;
            }
        }
    }
}

// ---------------------------------------------------------------------------
extern "C" void kernel_launch(void* const* d_in, const int* in_sizes, int n_in,
                              void* d_out, int out_size)
{
    const float* x      = (const float*)d_in[0];
    const float* qkv_w  = (const float*)d_in[1];
    const float* qkv_b  = (const float*)d_in[2];
    const float* proj_w = (const float*)d_in[3];
    const float* proj_b = (const float*)d_in[4];
    float* out = (float*)d_out;

    cudaFuncSetAttribute(k_qkv_gemm,  cudaFuncAttributeMaxDynamicSharedMemorySize, SMEM_BYTES);
    cudaFuncSetAttribute(k_proj_gemm, cudaFuncAttributeMaxDynamicSharedMemorySize, SMEM_BYTES);

    k_prep<<<131072 + 2048, 128>>>(x, qkv_w, proj_w);
    k_qkv_gemm<<<dim3(12, 1024), 256, SMEM_BYTES>>>(qkv_b);
    k_attn_mma<<<2048 * 8, 128>>>();
    k_proj_gemm<<<dim3(4, 1024), 256, SMEM_BYTES>>>(proj_b, out);
}

// round 10
// speedup vs baseline: 1.6581x; 1.1299x over previous
#include <cuda_runtime.h>
#include <cuda_fp16.h>
#include <cstdint>

// Problem constants:
// B=8, H=W=128, DIM=512, NH=8, HD=64, WIN=8x8 (N=64 tok/window), SHIFT=(4,4)
// windows: 2048 ; rows M = 131072

// Scratch (device globals = sanctioned scratch)
__device__ __half g_qkvh[3u * 2048u * 8u * 64u * 64u]; // [part][win][h][t][d] fp16; q,k RoPE'd
__device__ __half g_xh [131072u * 512u];               // gathered x, fp16
__device__ __half g_oh [131072u * 512u];               // attention out, fp16
__device__ __half g_wqh[1536u * 512u];                 // qkv_w fp16
__device__ __half g_wph[512u * 512u];                  // proj_w fp16

#define L2T16 0.8304820237218406f      // log2(10000)/16

// ---------------------------------------------------------------------------
// helpers
// ---------------------------------------------------------------------------
__device__ __forceinline__ void cp16(uint32_t smem, const void* gmem) {
    asm volatile("cp.async.cg.shared.global [%0], [%1], 16;\n" :: "r"(smem), "l"(gmem));
}
__device__ __forceinline__ void mma_f16(float* c, const uint32_t* a, const uint32_t* b) {
    asm volatile(
        "mma.sync.aligned.m16n8k16.row.col.f32.f16.f16.f32 "
        "{%0,%1,%2,%3}, {%4,%5,%6,%7}, {%8,%9}, {%0,%1,%2,%3};"
        : "+f"(c[0]), "+f"(c[1]), "+f"(c[2]), "+f"(c[3])
        : "r"(a[0]), "r"(a[1]), "r"(a[2]), "r"(a[3]), "r"(b[0]), "r"(b[1]));
}
__device__ __forceinline__ uint32_t pack_h2(float v0, float v1) {
    uint32_t p;
    asm("cvt.rn.f16x2.f32 %0, %1, %2;" : "=r"(p) : "f"(v1), "f"(v0));
    return p;
}

// fp16 GEMM smem geometry: rows of 32 halves padded to 40 (80 B)
#define HSTR32 20
#define STAGE_W (256 * HSTR32)
#define SMEM_BYTES (3 * STAGE_W * 4)    // 61440 B -> 2 CTAs/SM

// ---------------------------------------------------------------------------
// Kernel 0: prep — gather x (roll+partition) -> g_xh (fp16); weights -> fp16.
// ---------------------------------------------------------------------------
__global__ __launch_bounds__(128) void k_prep(const float* __restrict__ x,
                                              const float* __restrict__ qkv_w,
                                              const float* __restrict__ proj_w)
{
    const int bid = blockIdx.x;
    const int tid = threadIdx.x;

    const float* src;
    __half* dst;
    if (bid < 131072) {
        int m   = bid;
        int win = m >> 6, t = m & 63;
        int b   = win >> 8;
        int wh  = (win >> 4) & 15;
        int ww  = win & 15;
        int i   = t >> 3, j = t & 7;
        int r   = (wh * 8 + i + 4) & 127;     // roll(-4) gather
        int c   = (ww * 8 + j + 4) & 127;
        src = x + ((size_t)((((b << 7) | r) << 7) | c) << 9);
        dst = g_xh + (size_t)m * 512;
    } else {
        int w = bid - 131072;
        if (w < 1536) { src = qkv_w + (size_t)w * 512;           dst = g_wqh + (size_t)w * 512; }
        else          { src = proj_w + (size_t)(w - 1536) * 512; dst = g_wph + (size_t)(w - 1536) * 512; }
    }

    float4 v = ((const float4*)src)[tid];
    uint2 o;
    o.x = pack_h2(v.x, v.y);
    o.y = pack_h2(v.z, v.w);
    ((uint2*)dst)[tid] = o;
}

// ---------------------------------------------------------------------------
// fp16 GEMM core: BM=BN=128, BK=32, K=512, 256 threads, 8 warps (4M x 2N),
// warp tile 32x64, m16n8k16, 3-stage cp.async, 1 barrier/ktile, fp32 accum.
// ---------------------------------------------------------------------------
#define GEMM_MAIN(APTR, BPTR)                                                  \
    auto loadStage = [&](int s, int k0) {                                      \
        uint32_t ab = smemBase + s * (STAGE_W * 4);                            \
        uint32_t bb = ab + 128 * 80;                                           \
        _Pragma("unroll")                                                      \
        for (int it = 0; it < 2; it++) {                                       \
            int ch = tid + it * 256;                                           \
            int row = ch >> 2, ci = ch & 3;                                    \
            cp16(ab + row * 80 + ci * 16, APTR + (size_t)row * 512 + k0 + ci * 8); \
            cp16(bb + row * 80 + ci * 16, BPTR + (size_t)row * 512 + k0 + ci * 8); \
        }                                                                      \
    };                                                                         \
    loadStage(0, 0);                                                           \
    asm volatile("cp.async.commit_group;\n");                                  \
    loadStage(1, 32);                                                          \
    asm volatile("cp.async.commit_group;\n");                                  \
    asm volatile("cp.async.wait_group 1;\n");                                  \
    __syncthreads();                                                           \
    int ldS = 2, cpS = 0;                                                      \
    for (int kt = 0; kt < 16; kt++) {                                          \
        if (kt + 2 < 16) {                                                     \
            loadStage(ldS, (kt + 2) * 32);                                     \
            asm volatile("cp.async.commit_group;\n");                          \
            if (++ldS == 3) ldS = 0;                                           \
        }                                                                      \
        const uint32_t* As = sm32 + cpS * STAGE_W;                             \
        const uint32_t* Bs = As + 128 * HSTR32;                                \
        _Pragma("unroll")                                                      \
        for (int ks = 0; ks < 2; ks++) {                                       \
            uint32_t af[2][4];                                                 \
            _Pragma("unroll")                                                  \
            for (int mi = 0; mi < 2; mi++) {                                   \
                const uint32_t* ap = As + (warpM * 32 + mi * 16 + g) * HSTR32 + ks * 8 + t4; \
                af[mi][0] = ap[0];                                             \
                af[mi][1] = ap[8 * HSTR32];                                    \
                af[mi][2] = ap[4];                                             \
                af[mi][3] = ap[8 * HSTR32 + 4];                                \
            }                                                                  \
            _Pragma("unroll")                                                  \
            for (int ni = 0; ni < 8; ni++) {                                   \
                const uint32_t* bp = Bs + (warpN * 64 + ni * 8 + g) * HSTR32 + ks * 8 + t4; \
                uint32_t bf[2] = { bp[0], bp[4] };                             \
                mma_f16(acc[0][ni], af[0], bf);                                \
                mma_f16(acc[1][ni], af[1], bf);                                \
            }                                                                  \
        }                                                                      \
        if (++cpS == 3) cpS = 0;                                               \
        if (kt < 15) {                                                         \
            if (kt + 2 < 16) asm volatile("cp.async.wait_group 1;\n");         \
            else             asm volatile("cp.async.wait_group 0;\n");         \
            __syncthreads();                                                   \
        }                                                                      \
    }

// ---------------------------------------------------------------------------
// Kernel 1: QKV GEMM (fp16) + bias + fused RoPE/scale + fp16 pack -> g_qkvh.
//   M=131072 K=512 N=1536
// Warp's 64 n-cols = exactly one (part, head): part/h warp-uniform.
// RoPE pair (d, d+16) = acc pair (ni, ni+2) of the SAME thread.
// ---------------------------------------------------------------------------
__global__ __launch_bounds__(256, 2) void k_qkv_gemm(const float* __restrict__ bias)
{
    extern __shared__ uint32_t sm32[];
    const uint32_t smemBase = (uint32_t)__cvta_generic_to_shared(sm32);

    const int tid   = threadIdx.x;
    const int nTile = blockIdx.x;
    const int mTile = blockIdx.y;

    const int warpId = tid >> 5, lane = tid & 31;
    const int warpM  = warpId & 3;
    const int warpN  = warpId >> 2;
    const int n0     = nTile * 128;
    const int g      = lane >> 2, t4 = lane & 3;

    float acc[2][8][4];
#pragma unroll
    for (int mi = 0; mi < 2; mi++)
#pragma unroll
        for (int ni = 0; ni < 8; ni++)
#pragma unroll
            for (int e = 0; e < 4; e++) acc[mi][ni][e] = 0.f;

    const __half* Ag = g_xh + (size_t)(mTile * 128) * 512;
    const __half* Bg = g_wqh + (size_t)n0 * 512;
    GEMM_MAIN(Ag, Bg)

    const int nbase = n0 + warpN * 64;     // 64-aligned
    const int part  = nbase >> 9;
    const int h     = (nbase >> 6) & 7;

    // bias (reference: GEMM + b, THEN rope)
#pragma unroll
    for (int ni = 0; ni < 8; ni++) {
        int n = nbase + ni * 8 + 2 * t4;
        float b0 = bias[n], b1 = bias[n + 1];
#pragma unroll
        for (int mi = 0; mi < 2; mi++) {
            acc[mi][ni][0] += b0; acc[mi][ni][1] += b1;
            acc[mi][ni][2] += b0; acc[mi][ni][3] += b1;
        }
    }

    if (part < 2) {
        const float scale = (part == 0) ? 0.125f : 1.0f;
        float invv[2][2];  // [ni&1][j]: e = (ni&1)*8 + 2*t4 + j
#pragma unroll
        for (int p = 0; p < 2; p++)
#pragma unroll
            for (int j = 0; j < 2; j++)
                invv[p][j] = exp2f(-(float)(p * 8 + 2 * t4 + j) * L2T16);

#pragma unroll
        for (int mi = 0; mi < 2; mi++) {
#pragma unroll
            for (int rr = 0; rr < 2; rr++) {
                int t = (mTile * 128 + warpM * 32 + mi * 16 + g + rr * 8) & 63;
                float posR = (float)(t >> 3), posC = (float)(t & 7);
#pragma unroll
                for (int q = 0; q < 4; q++) {
                    const int niList[4] = {0, 1, 4, 5};
                    int ni = niList[q];
                    float pos = (ni < 4) ? posR : posC;
#pragma unroll
                    for (int j = 0; j < 2; j++) {
                        float ang = pos * invv[ni & 1][j];
                        float sv, cv;
                        __sincosf(ang, &sv, &cv);
                        float a = acc[mi][ni][rr * 2 + j];
                        float b = acc[mi][ni + 2][rr * 2 + j];
                        acc[mi][ni][rr * 2 + j]     = (a * cv - b * sv) * scale;
                        acc[mi][ni + 2][rr * 2 + j] = (b * cv + a * sv) * scale;
                    }
                }
            }
        }
    }

    // pack fp16 + scatter into g_qkvh[part][win][h][t][d]
    uint32_t* gq = (uint32_t*)g_qkvh;
#pragma unroll
    for (int ni = 0; ni < 8; ni++) {
        int d0 = ni * 8 + 2 * t4;          // even
#pragma unroll
        for (int mi = 0; mi < 2; mi++) {
#pragma unroll
            for (int rr = 0; rr < 2; rr++) {
                int m   = mTile * 128 + warpM * 32 + mi * 16 + g + rr * 8;
                int win = m >> 6, t = m & 63;
                size_t idx = ((((size_t)part * 2048 + win) * 8 + h) * 64 + t) * 64 + d0;
                gq[idx >> 1] = pack_h2(acc[mi][ni][rr * 2 + 0], acc[mi][ni][rr * 2 + 1]);
            }
        }
    }
}

// ---------------------------------------------------------------------------
// Kernel 2: per (window, head) attention, all-fp16 MMA (fp32 accum/softmax).
// 128 threads; warp w owns rows [16w,16w+16). ONE __syncthreads total.
// ---------------------------------------------------------------------------
#define ASTW 36   // words per 64-half row (32 data + 4 pad)

__global__ __launch_bounds__(128) void k_attn_f16()
{
    __shared__ uint32_t Qs[64 * ASTW];   // Q [t][d]; P overlays own strip
    __shared__ uint32_t Ks[64 * ASTW];   // K [t][d]
    __shared__ uint32_t Vs[64 * ASTW];   // V [d][t] (transposed at load)

    const int tid  = threadIdx.x;
    const int warp = tid >> 5;
    const int lane = tid & 31;
    const int g    = lane >> 2;          // 0..7
    const int c    = lane & 3;           // 0..3
    const int m0   = warp * 16;

    const int win = blockIdx.x >> 3;
    const int h   = blockIdx.x & 7;

    const size_t qoff = ((size_t)win * 8 + h) * 4096;       // halves
    const size_t pstr = (size_t)2048 * 8 * 4096;
    const uint4* qg = (const uint4*)(g_qkvh + qoff);
    const uint4* kg = (const uint4*)(g_qkvh + pstr + qoff);
    const uint4* vg = (const uint4*)(g_qkvh + 2 * pstr + qoff);
    __half* VsH = (__half*)Vs;

#pragma unroll
    for (int it = 0; it < 4; it++) {
        int e4 = tid + it * 128;         // 0..511
        int t  = e4 >> 3;
        int ci = e4 & 7;                 // 8-half chunk
        *(uint4*)(Qs + t * ASTW + ci * 4) = qg[e4];
        *(uint4*)(Ks + t * ASTW + ci * 4) = kg[e4];
        uint4 w = vg[e4];                // 8 halves: d = ci*8..ci*8+7 at row t
        const __half* hb = (const __half*)&w;
#pragma unroll
        for (int k = 0; k < 8; k++)
            VsH[(ci * 8 + k) * (2 * ASTW) + t] = hb[k];
    }
    __syncthreads();

    // ---- S = Q K^T (fp16 mma, k16 x 4) ----
    uint32_t areg[4][4];
#pragma unroll
    for (int ks = 0; ks < 4; ks++) {
        const uint32_t* ap = Qs + (m0 + g) * ASTW + ks * 8 + c;
        areg[ks][0] = ap[0];
        areg[ks][1] = ap[8 * ASTW];
        areg[ks][2] = ap[4];
        areg[ks][3] = ap[8 * ASTW + 4];
    }

    float sacc[8][4];
#pragma unroll
    for (int ni = 0; ni < 8; ni++)
#pragma unroll
        for (int e = 0; e < 4; e++) sacc[ni][e] = 0.f;

#pragma unroll
    for (int ni = 0; ni < 8; ni++) {
        const uint32_t* bb = Ks + (ni * 8 + g) * ASTW + c;
#pragma unroll
        for (int ks = 0; ks < 4; ks++) {
            uint32_t bf[2] = { bb[ks * 8], bb[ks * 8 + 4] };
            mma_f16(sacc[ni], areg[ks], bf);
        }
    }

    // ---- mask + softmax in registers ----
    const bool maskOn = (((win >> 4) & 15) == 15);
    const bool warpLo = (warp < 2);

    float mx1 = -1e30f, mx2 = -1e30f;
#pragma unroll
    for (int ni = 0; ni < 8; ni++) {
        float msub = (maskOn && ((ni < 4) != warpLo)) ? 100.f : 0.f;
        sacc[ni][0] -= msub; sacc[ni][1] -= msub;
        sacc[ni][2] -= msub; sacc[ni][3] -= msub;
        mx1 = fmaxf(mx1, fmaxf(sacc[ni][0], sacc[ni][1]));
        mx2 = fmaxf(mx2, fmaxf(sacc[ni][2], sacc[ni][3]));
    }
    mx1 = fmaxf(mx1, __shfl_xor_sync(0xffffffffu, mx1, 1));
    mx1 = fmaxf(mx1, __shfl_xor_sync(0xffffffffu, mx1, 2));
    mx2 = fmaxf(mx2, __shfl_xor_sync(0xffffffffu, mx2, 1));
    mx2 = fmaxf(mx2, __shfl_xor_sync(0xffffffffu, mx2, 2));

    float s1 = 0.f, s2 = 0.f;
#pragma unroll
    for (int ni = 0; ni < 8; ni++) {
        sacc[ni][0] = __expf(sacc[ni][0] - mx1);
        sacc[ni][1] = __expf(sacc[ni][1] - mx1);
        sacc[ni][2] = __expf(sacc[ni][2] - mx2);
        sacc[ni][3] = __expf(sacc[ni][3] - mx2);
        s1 += sacc[ni][0] + sacc[ni][1];
        s2 += sacc[ni][2] + sacc[ni][3];
    }
    s1 += __shfl_xor_sync(0xffffffffu, s1, 1);
    s1 += __shfl_xor_sync(0xffffffffu, s1, 2);
    s2 += __shfl_xor_sync(0xffffffffu, s2, 1);
    s2 += __shfl_xor_sync(0xffffffffu, s2, 2);
    const float i1 = 1.f / s1, i2 = 1.f / s2;

    // store P (fp16) into OWN 16-row strip of Qs — no other warp reads it
#pragma unroll
    for (int ni = 0; ni < 8; ni++) {
        Qs[(m0 + g) * ASTW + ni * 4 + c]     = pack_h2(sacc[ni][0] * i1, sacc[ni][1] * i1);
        Qs[(m0 + g + 8) * ASTW + ni * 4 + c] = pack_h2(sacc[ni][2] * i2, sacc[ni][3] * i2);
    }
    __syncwarp();

    // ---- O = P V (fp16 mma; V already [d][t] in Vs) ----
    uint32_t preg[4][4];
#pragma unroll
    for (int ks = 0; ks < 4; ks++) {
        const uint32_t* pp = Qs + (m0 + g) * ASTW + ks * 8 + c;
        preg[ks][0] = pp[0];
        preg[ks][1] = pp[8 * ASTW];
        preg[ks][2] = pp[4];
        preg[ks][3] = pp[8 * ASTW + 4];
    }

    float oacc[8][4];
#pragma unroll
    for (int ni = 0; ni < 8; ni++)
#pragma unroll
        for (int e = 0; e < 4; e++) oacc[ni][e] = 0.f;

#pragma unroll
    for (int ni = 0; ni < 8; ni++) {
        const uint32_t* bb = Vs + (ni * 8 + g) * ASTW + c;
#pragma unroll
        for (int ks = 0; ks < 4; ks++) {
            uint32_t bf[2] = { bb[ks * 8], bb[ks * 8 + 4] };
            mma_f16(oacc[ni], preg[ks], bf);
        }
    }

    // store O as fp16 into g_oh[m][h*64+d]
    uint32_t* goh = (uint32_t*)g_oh;
    const size_t mrow1 = (size_t)win * 64 + m0 + g;
    const size_t mrow2 = mrow1 + 8;
#pragma unroll
    for (int ni = 0; ni < 8; ni++) {
        int d0 = h * 64 + ni * 8 + 2 * c;
        goh[(mrow1 * 512 + d0) >> 1] = pack_h2(oacc[ni][0], oacc[ni][1]);
        goh[(mrow2 * 512 + d0) >> 1] = pack_h2(oacc[ni][2], oacc[ni][3]);
    }
}

// ---------------------------------------------------------------------------
// Kernel 3: proj GEMM (fp16) + bias + unpartition/roll scatter.
//   M=131072 K=512 N=512
// ---------------------------------------------------------------------------
__global__ __launch_bounds__(256, 2) void k_proj_gemm(const float* __restrict__ bias,
                                                      float* __restrict__ out)
{
    extern __shared__ uint32_t sm32[];
    const uint32_t smemBase = (uint32_t)__cvta_generic_to_shared(sm32);

    const int tid   = threadIdx.x;
    const int nTile = blockIdx.x;
    const int mTile = blockIdx.y;

    const int warpId = tid >> 5, lane = tid & 31;
    const int warpM  = warpId & 3;
    const int warpN  = warpId >> 2;
    const int n0     = nTile * 128;
    const int g      = lane >> 2, t4 = lane & 3;

    float acc[2][8][4];
#pragma unroll
    for (int mi = 0; mi < 2; mi++)
#pragma unroll
        for (int ni = 0; ni < 8; ni++)
#pragma unroll
            for (int e = 0; e < 4; e++) acc[mi][ni][e] = 0.f;

    const __half* Ag = g_oh + (size_t)(mTile * 128) * 512;
    const __half* Bg = g_wph + (size_t)n0 * 512;
    GEMM_MAIN(Ag, Bg)

#pragma unroll
    for (int ni = 0; ni < 8; ni++) {
        int n  = n0 + warpN * 64 + ni * 8 + 2 * t4;
        float b0 = bias[n], b1 = bias[n + 1];
#pragma unroll
        for (int mi = 0; mi < 2; mi++) {
#pragma unroll
            for (int rr2 = 0; rr2 < 2; rr2++) {
                int m   = mTile * 128 + warpM * 32 + mi * 16 + g + rr2 * 8;
                int win = m >> 6, tt = m & 63;
                int b   = win >> 8;
                int wh  = (win >> 4) & 15;
                int ww  = win & 15;
                int ii  = tt >> 3, jj = tt & 7;
                int rO  = (wh * 8 + ii + 4) & 127;
                int cO  = (ww * 8 + jj + 4) & 127;
                size_t off = ((((size_t)b << 7) | rO) << 7 | cO) << 9;
                float2 v = make_float2(acc[mi][ni][rr2 * 2 + 0] + b0,
                                       acc[mi][ni][rr2 * 2 + 1] + b1);
                *(float2*)(out + off + n) = v;
            }
        }
    }
}

// ---------------------------------------------------------------------------
extern "C" void kernel_launch(void* const* d_in, const int* in_sizes, int n_in,
                              void* d_out, int out_size)
{
    const float* x      = (const float*)d_in[0];
    const float* qkv_w  = (const float*)d_in[1];
    const float* qkv_b  = (const float*)d_in[2];
    const float* proj_w = (const float*)d_in[3];
    const float* proj_b = (const float*)d_in[4];
    float* out = (float*)d_out;

    cudaFuncSetAttribute(k_qkv_gemm,  cudaFuncAttributeMaxDynamicSharedMemorySize, SMEM_BYTES);
    cudaFuncSetAttribute(k_proj_gemm, cudaFuncAttributeMaxDynamicSharedMemorySize, SMEM_BYTES);

    k_prep<<<131072 + 2048, 128>>>(x, qkv_w, proj_w);
    k_qkv_gemm<<<dim3(12, 1024), 256, SMEM_BYTES>>>(qkv_b);
    k_attn_f16<<<2048 * 8, 128>>>();
    k_proj_gemm<<<dim3(4, 1024), 256, SMEM_BYTES>>>(proj_b, out);
}

// round 11
// speedup vs baseline: 1.9346x; 1.1667x over previous
#include <cuda_runtime.h>
#include <cuda_fp16.h>
#include <cstdint>

// Problem constants:
// B=8, H=W=128, DIM=512, NH=8, HD=64, WIN=8x8 (N=64 tok/window), SHIFT=(4,4)
// windows: 2048 ; rows M = 131072

// Scratch (device globals = sanctioned scratch)
__device__ __half g_qkvh[3u * 2048u * 8u * 64u * 64u]; // [part][win][h][t][d] fp16; q,k RoPE'd
__device__ __half g_xh [131072u * 512u];               // gathered x, fp16
__device__ __half g_oh [131072u * 512u];               // attention out, fp16
__device__ __half g_wqh[1536u * 512u];                 // qkv_w fp16
__device__ __half g_wph[512u * 512u];                  // proj_w fp16

#define L2T16 0.8304820237218406f      // log2(10000)/16

// ---------------------------------------------------------------------------
// helpers
// ---------------------------------------------------------------------------
__device__ __forceinline__ void cp16(uint32_t smem, const void* gmem) {
    asm volatile("cp.async.cg.shared.global [%0], [%1], 16;\n" :: "r"(smem), "l"(gmem));
}
__device__ __forceinline__ void mma_f16(float* c, const uint32_t* a, const uint32_t* b) {
    asm volatile(
        "mma.sync.aligned.m16n8k16.row.col.f32.f16.f16.f32 "
        "{%0,%1,%2,%3}, {%4,%5,%6,%7}, {%8,%9}, {%0,%1,%2,%3};"
        : "+f"(c[0]), "+f"(c[1]), "+f"(c[2]), "+f"(c[3])
        : "r"(a[0]), "r"(a[1]), "r"(a[2]), "r"(a[3]), "r"(b[0]), "r"(b[1]));
}
__device__ __forceinline__ uint32_t pack_h2(float v0, float v1) {
    uint32_t p;
    asm("cvt.rn.f16x2.f32 %0, %1, %2;" : "=r"(p) : "f"(v1), "f"(v0));
    return p;
}
__device__ __forceinline__ void ldsm_x4(uint32_t* d, uint32_t addr) {
    asm volatile("ldmatrix.sync.aligned.m8n8.x4.shared.b16 {%0,%1,%2,%3}, [%4];"
                 : "=r"(d[0]), "=r"(d[1]), "=r"(d[2]), "=r"(d[3]) : "r"(addr));
}
__device__ __forceinline__ void ldsm_x2(uint32_t* d, uint32_t addr) {
    asm volatile("ldmatrix.sync.aligned.m8n8.x2.shared.b16 {%0,%1}, [%2];"
                 : "=r"(d[0]), "=r"(d[1]) : "r"(addr));
}

// GEMM smem geometry (BK=64): rows of 64 halves + 16B pad = 144 bytes.
#define ROWB 144
#define STAGE_B (256 * ROWB)            // A(128 rows) + B(128 rows) = 36864 B
#define SMEM_BYTES (3 * STAGE_B)        // 110592 B -> 2 CTAs/SM

// ---------------------------------------------------------------------------
// Kernel 0: prep — gather x (roll+partition) -> g_xh (fp16); weights -> fp16.
// ---------------------------------------------------------------------------
__global__ __launch_bounds__(128) void k_prep(const float* __restrict__ x,
                                              const float* __restrict__ qkv_w,
                                              const float* __restrict__ proj_w)
{
    const int bid = blockIdx.x;
    const int tid = threadIdx.x;

    const float* src;
    __half* dst;
    if (bid < 131072) {
        int m   = bid;
        int win = m >> 6, t = m & 63;
        int b   = win >> 8;
        int wh  = (win >> 4) & 15;
        int ww  = win & 15;
        int i   = t >> 3, j = t & 7;
        int r   = (wh * 8 + i + 4) & 127;     // roll(-4) gather
        int c   = (ww * 8 + j + 4) & 127;
        src = x + ((size_t)((((b << 7) | r) << 7) | c) << 9);
        dst = g_xh + (size_t)m * 512;
    } else {
        int w = bid - 131072;
        if (w < 1536) { src = qkv_w + (size_t)w * 512;           dst = g_wqh + (size_t)w * 512; }
        else          { src = proj_w + (size_t)(w - 1536) * 512; dst = g_wph + (size_t)(w - 1536) * 512; }
    }

    float4 v = ((const float4*)src)[tid];
    uint2 o;
    o.x = pack_h2(v.x, v.y);
    o.y = pack_h2(v.z, v.w);
    ((uint2*)dst)[tid] = o;
}

// ---------------------------------------------------------------------------
// fp16 GEMM core: BM=BN=128, BK=64, K=512 (8 ktiles), 256 threads,
// 8 warps (4M x 2N), warp tile 32x64, m16n8k16, ldmatrix fragments,
// 3-stage cp.async, 1 barrier per ktile, fp32 accumulators.
// ---------------------------------------------------------------------------
#define GEMM_MAIN(APTR, BPTR)                                                  \
    /* per-lane ldmatrix base addresses (byte offsets within a stage) */       \
    const int q_  = lane >> 3, r_ = lane & 7;                                  \
    uint32_t aLane[2];                                                         \
    _Pragma("unroll")                                                          \
    for (int mi = 0; mi < 2; mi++)                                             \
        aLane[mi] = (uint32_t)((warpM * 32 + mi * 16 + (q_ & 1) * 8 + r_) * ROWB \
                               + (q_ >> 1) * 16);                              \
    const uint32_t bLane = (uint32_t)(128 * ROWB +                             \
        (warpN * 64 + r_) * ROWB + ((lane >> 3) & 1) * 16);                    \
    auto loadStage = [&](int s, int k0) {                                      \
        uint32_t ab = smemBase + s * STAGE_B;                                  \
        uint32_t bb = ab + 128 * ROWB;                                         \
        _Pragma("unroll")                                                      \
        for (int it = 0; it < 4; it++) {                                       \
            int ch = tid + it * 256;          /* 0..1023 */                    \
            int row = ch >> 3, ci = ch & 7;                                    \
            cp16(ab + row * ROWB + ci * 16, APTR + (size_t)row * 512 + k0 + ci * 8); \
            cp16(bb + row * ROWB + ci * 16, BPTR + (size_t)row * 512 + k0 + ci * 8); \
        }                                                                      \
    };                                                                         \
    loadStage(0, 0);                                                           \
    asm volatile("cp.async.commit_group;\n");                                  \
    loadStage(1, 64);                                                          \
    asm volatile("cp.async.commit_group;\n");                                  \
    asm volatile("cp.async.wait_group 1;\n");                                  \
    __syncthreads();                                                           \
    int ldS = 2, cpS = 0;                                                      \
    for (int kt = 0; kt < 8; kt++) {                                           \
        if (kt + 2 < 8) {                                                      \
            loadStage(ldS, (kt + 2) * 64);                                     \
            asm volatile("cp.async.commit_group;\n");                          \
            if (++ldS == 3) ldS = 0;                                           \
        }                                                                      \
        const uint32_t stA = smemBase + cpS * STAGE_B;                         \
        _Pragma("unroll")                                                      \
        for (int ks = 0; ks < 4; ks++) {                                       \
            uint32_t af[2][4];                                                 \
            ldsm_x4(af[0], stA + aLane[0] + ks * 32);                          \
            ldsm_x4(af[1], stA + aLane[1] + ks * 32);                          \
            _Pragma("unroll")                                                  \
            for (int ni = 0; ni < 8; ni++) {                                   \
                uint32_t bf[2];                                                \
                ldsm_x2(bf, stA + bLane + ni * (8 * ROWB) + ks * 32);          \
                mma_f16(acc[0][ni], af[0], bf);                                \
                mma_f16(acc[1][ni], af[1], bf);                                \
            }                                                                  \
        }                                                                      \
        if (++cpS == 3) cpS = 0;                                               \
        if (kt < 7) {                                                          \
            if (kt + 2 < 8) asm volatile("cp.async.wait_group 1;\n");          \
            else            asm volatile("cp.async.wait_group 0;\n");          \
            __syncthreads();                                                   \
        }                                                                      \
    }

// ---------------------------------------------------------------------------
// Kernel 1: QKV GEMM (fp16) + bias + fused RoPE/scale + fp16 pack -> g_qkvh.
//   M=131072 K=512 N=1536
// ---------------------------------------------------------------------------
__global__ __launch_bounds__(256, 2) void k_qkv_gemm(const float* __restrict__ bias)
{
    extern __shared__ uint32_t sm32[];
    const uint32_t smemBase = (uint32_t)__cvta_generic_to_shared(sm32);

    const int tid   = threadIdx.x;
    const int nTile = blockIdx.x;
    const int mTile = blockIdx.y;

    const int warpId = tid >> 5, lane = tid & 31;
    const int warpM  = warpId & 3;
    const int warpN  = warpId >> 2;
    const int n0     = nTile * 128;
    const int g      = lane >> 2, t4 = lane & 3;

    float acc[2][8][4];
#pragma unroll
    for (int mi = 0; mi < 2; mi++)
#pragma unroll
        for (int ni = 0; ni < 8; ni++)
#pragma unroll
            for (int e = 0; e < 4; e++) acc[mi][ni][e] = 0.f;

    const __half* Ag = g_xh + (size_t)(mTile * 128) * 512;
    const __half* Bg = g_wqh + (size_t)n0 * 512;
    GEMM_MAIN(Ag, Bg)

    const int nbase = n0 + warpN * 64;     // 64-aligned -> one (part, head)
    const int part  = nbase >> 9;
    const int h     = (nbase >> 6) & 7;

    // bias (reference: GEMM + b, THEN rope)
#pragma unroll
    for (int ni = 0; ni < 8; ni++) {
        int n = nbase + ni * 8 + 2 * t4;
        float b0 = bias[n], b1 = bias[n + 1];
#pragma unroll
        for (int mi = 0; mi < 2; mi++) {
            acc[mi][ni][0] += b0; acc[mi][ni][1] += b1;
            acc[mi][ni][2] += b0; acc[mi][ni][3] += b1;
        }
    }

    if (part < 2) {
        const float scale = (part == 0) ? 0.125f : 1.0f;
        float invv[2][2];  // [ni&1][j]: e = (ni&1)*8 + 2*t4 + j
#pragma unroll
        for (int p = 0; p < 2; p++)
#pragma unroll
            for (int j = 0; j < 2; j++)
                invv[p][j] = exp2f(-(float)(p * 8 + 2 * t4 + j) * L2T16);

#pragma unroll
        for (int mi = 0; mi < 2; mi++) {
#pragma unroll
            for (int rr = 0; rr < 2; rr++) {
                int t = (mTile * 128 + warpM * 32 + mi * 16 + g + rr * 8) & 63;
                float posR = (float)(t >> 3), posC = (float)(t & 7);
#pragma unroll
                for (int qq = 0; qq < 4; qq++) {
                    const int niList[4] = {0, 1, 4, 5};
                    int ni = niList[qq];
                    float pos = (ni < 4) ? posR : posC;
#pragma unroll
                    for (int j = 0; j < 2; j++) {
                        float ang = pos * invv[ni & 1][j];
                        float sv, cv;
                        __sincosf(ang, &sv, &cv);
                        float a = acc[mi][ni][rr * 2 + j];
                        float b = acc[mi][ni + 2][rr * 2 + j];
                        acc[mi][ni][rr * 2 + j]     = (a * cv - b * sv) * scale;
                        acc[mi][ni + 2][rr * 2 + j] = (b * cv + a * sv) * scale;
                    }
                }
            }
        }
    }

    // pack fp16 + scatter into g_qkvh[part][win][h][t][d]
    uint32_t* gq = (uint32_t*)g_qkvh;
#pragma unroll
    for (int ni = 0; ni < 8; ni++) {
        int d0 = ni * 8 + 2 * t4;          // even
#pragma unroll
        for (int mi = 0; mi < 2; mi++) {
#pragma unroll
            for (int rr = 0; rr < 2; rr++) {
                int m   = mTile * 128 + warpM * 32 + mi * 16 + g + rr * 8;
                int win = m >> 6, t = m & 63;
                size_t idx = ((((size_t)part * 2048 + win) * 8 + h) * 64 + t) * 64 + d0;
                gq[idx >> 1] = pack_h2(acc[mi][ni][rr * 2 + 0], acc[mi][ni][rr * 2 + 1]);
            }
        }
    }
}

// ---------------------------------------------------------------------------
// Kernel 2: per (window, head) attention, all-fp16 MMA (fp32 accum/softmax).
// 128 threads; warp w owns rows [16w,16w+16). ONE __syncthreads total.
// ---------------------------------------------------------------------------
#define ASTW 36   // words per 64-half row (32 data + 4 pad)

__global__ __launch_bounds__(128) void k_attn_f16()
{
    __shared__ uint32_t Qs[64 * ASTW];   // Q [t][d]; P overlays own strip
    __shared__ uint32_t Ks[64 * ASTW];   // K [t][d]
    __shared__ uint32_t Vs[64 * ASTW];   // V [d][t] (transposed at load)

    const int tid  = threadIdx.x;
    const int warp = tid >> 5;
    const int lane = tid & 31;
    const int g    = lane >> 2;
    const int c    = lane & 3;
    const int m0   = warp * 16;

    const int win = blockIdx.x >> 3;
    const int h   = blockIdx.x & 7;

    const size_t qoff = ((size_t)win * 8 + h) * 4096;
    const size_t pstr = (size_t)2048 * 8 * 4096;
    const uint4* qg = (const uint4*)(g_qkvh + qoff);
    const uint4* kg = (const uint4*)(g_qkvh + pstr + qoff);
    const uint4* vg = (const uint4*)(g_qkvh + 2 * pstr + qoff);
    __half* VsH = (__half*)Vs;

#pragma unroll
    for (int it = 0; it < 4; it++) {
        int e4 = tid + it * 128;
        int t  = e4 >> 3;
        int ci = e4 & 7;
        *(uint4*)(Qs + t * ASTW + ci * 4) = qg[e4];
        *(uint4*)(Ks + t * ASTW + ci * 4) = kg[e4];
        uint4 w = vg[e4];
        const __half* hb = (const __half*)&w;
#pragma unroll
        for (int k = 0; k < 8; k++)
            VsH[(ci * 8 + k) * (2 * ASTW) + t] = hb[k];
    }
    __syncthreads();

    uint32_t areg[4][4];
#pragma unroll
    for (int ks = 0; ks < 4; ks++) {
        const uint32_t* ap = Qs + (m0 + g) * ASTW + ks * 8 + c;
        areg[ks][0] = ap[0];
        areg[ks][1] = ap[8 * ASTW];
        areg[ks][2] = ap[4];
        areg[ks][3] = ap[8 * ASTW + 4];
    }

    float sacc[8][4];
#pragma unroll
    for (int ni = 0; ni < 8; ni++)
#pragma unroll
        for (int e = 0; e < 4; e++) sacc[ni][e] = 0.f;

#pragma unroll
    for (int ni = 0; ni < 8; ni++) {
        const uint32_t* bb = Ks + (ni * 8 + g) * ASTW + c;
#pragma unroll
        for (int ks = 0; ks < 4; ks++) {
            uint32_t bf[2] = { bb[ks * 8], bb[ks * 8 + 4] };
            mma_f16(sacc[ni], areg[ks], bf);
        }
    }

    const bool maskOn = (((win >> 4) & 15) == 15);
    const bool warpLo = (warp < 2);

    float mx1 = -1e30f, mx2 = -1e30f;
#pragma unroll
    for (int ni = 0; ni < 8; ni++) {
        float msub = (maskOn && ((ni < 4) != warpLo)) ? 100.f : 0.f;
        sacc[ni][0] -= msub; sacc[ni][1] -= msub;
        sacc[ni][2] -= msub; sacc[ni][3] -= msub;
        mx1 = fmaxf(mx1, fmaxf(sacc[ni][0], sacc[ni][1]));
        mx2 = fmaxf(mx2, fmaxf(sacc[ni][2], sacc[ni][3]));
    }
    mx1 = fmaxf(mx1, __shfl_xor_sync(0xffffffffu, mx1, 1));
    mx1 = fmaxf(mx1, __shfl_xor_sync(0xffffffffu, mx1, 2));
    mx2 = fmaxf(mx2, __shfl_xor_sync(0xffffffffu, mx2, 1));
    mx2 = fmaxf(mx2, __shfl_xor_sync(0xffffffffu, mx2, 2));

    float s1 = 0.f, s2 = 0.f;
#pragma unroll
    for (int ni = 0; ni < 8; ni++) {
        sacc[ni][0] = __expf(sacc[ni][0] - mx1);
        sacc[ni][1] = __expf(sacc[ni][1] - mx1);
        sacc[ni][2] = __expf(sacc[ni][2] - mx2);
        sacc[ni][3] = __expf(sacc[ni][3] - mx2);
        s1 += sacc[ni][0] + sacc[ni][1];
        s2 += sacc[ni][2] + sacc[ni][3];
    }
    s1 += __shfl_xor_sync(0xffffffffu, s1, 1);
    s1 += __shfl_xor_sync(0xffffffffu, s1, 2);
    s2 += __shfl_xor_sync(0xffffffffu, s2, 1);
    s2 += __shfl_xor_sync(0xffffffffu, s2, 2);
    const float i1 = 1.f / s1, i2 = 1.f / s2;

#pragma unroll
    for (int ni = 0; ni < 8; ni++) {
        Qs[(m0 + g) * ASTW + ni * 4 + c]     = pack_h2(sacc[ni][0] * i1, sacc[ni][1] * i1);
        Qs[(m0 + g + 8) * ASTW + ni * 4 + c] = pack_h2(sacc[ni][2] * i2, sacc[ni][3] * i2);
    }
    __syncwarp();

    uint32_t preg[4][4];
#pragma unroll
    for (int ks = 0; ks < 4; ks++) {
        const uint32_t* pp = Qs + (m0 + g) * ASTW + ks * 8 + c;
        preg[ks][0] = pp[0];
        preg[ks][1] = pp[8 * ASTW];
        preg[ks][2] = pp[4];
        preg[ks][3] = pp[8 * ASTW + 4];
    }

    float oacc[8][4];
#pragma unroll
    for (int ni = 0; ni < 8; ni++)
#pragma unroll
        for (int e = 0; e < 4; e++) oacc[ni][e] = 0.f;

#pragma unroll
    for (int ni = 0; ni < 8; ni++) {
        const uint32_t* bb = Vs + (ni * 8 + g) * ASTW + c;
#pragma unroll
        for (int ks = 0; ks < 4; ks++) {
            uint32_t bf[2] = { bb[ks * 8], bb[ks * 8 + 4] };
            mma_f16(oacc[ni], preg[ks], bf);
        }
    }

    uint32_t* goh = (uint32_t*)g_oh;
    const size_t mrow1 = (size_t)win * 64 + m0 + g;
    const size_t mrow2 = mrow1 + 8;
#pragma unroll
    for (int ni = 0; ni < 8; ni++) {
        int d0 = h * 64 + ni * 8 + 2 * c;
        goh[(mrow1 * 512 + d0) >> 1] = pack_h2(oacc[ni][0], oacc[ni][1]);
        goh[(mrow2 * 512 + d0) >> 1] = pack_h2(oacc[ni][2], oacc[ni][3]);
    }
}

// ---------------------------------------------------------------------------
// Kernel 3: proj GEMM (fp16) + bias + unpartition/roll scatter.
//   M=131072 K=512 N=512
// ---------------------------------------------------------------------------
__global__ __launch_bounds__(256, 2) void k_proj_gemm(const float* __restrict__ bias,
                                                      float* __restrict__ out)
{
    extern __shared__ uint32_t sm32[];
    const uint32_t smemBase = (uint32_t)__cvta_generic_to_shared(sm32);

    const int tid   = threadIdx.x;
    const int nTile = blockIdx.x;
    const int mTile = blockIdx.y;

    const int warpId = tid >> 5, lane = tid & 31;
    const int warpM  = warpId & 3;
    const int warpN  = warpId >> 2;
    const int n0     = nTile * 128;
    const int g      = lane >> 2, t4 = lane & 3;

    float acc[2][8][4];
#pragma unroll
    for (int mi = 0; mi < 2; mi++)
#pragma unroll
        for (int ni = 0; ni < 8; ni++)
#pragma unroll
            for (int e = 0; e < 4; e++) acc[mi][ni][e] = 0.f;

    const __half* Ag = g_oh + (size_t)(mTile * 128) * 512;
    const __half* Bg = g_wph + (size_t)n0 * 512;
    GEMM_MAIN(Ag, Bg)

#pragma unroll
    for (int ni = 0; ni < 8; ni++) {
        int n  = n0 + warpN * 64 + ni * 8 + 2 * t4;
        float b0 = bias[n], b1 = bias[n + 1];
#pragma unroll
        for (int mi = 0; mi < 2; mi++) {
#pragma unroll
            for (int rr2 = 0; rr2 < 2; rr2++) {
                int m   = mTile * 128 + warpM * 32 + mi * 16 + g + rr2 * 8;
                int win = m >> 6, tt = m & 63;
                int b   = win >> 8;
                int wh  = (win >> 4) & 15;
                int ww  = win & 15;
                int ii  = tt >> 3, jj = tt & 7;
                int rO  = (wh * 8 + ii + 4) & 127;
                int cO  = (ww * 8 + jj + 4) & 127;
                size_t off = ((((size_t)b << 7) | rO) << 7 | cO) << 9;
                float2 v = make_float2(acc[mi][ni][rr2 * 2 + 0] + b0,
                                       acc[mi][ni][rr2 * 2 + 1] + b1);
                *(float2*)(out + off + n) = v;
            }
        }
    }
}

// ---------------------------------------------------------------------------
extern "C" void kernel_launch(void* const* d_in, const int* in_sizes, int n_in,
                              void* d_out, int out_size)
{
    const float* x      = (const float*)d_in[0];
    const float* qkv_w  = (const float*)d_in[1];
    const float* qkv_b  = (const float*)d_in[2];
    const float* proj_w = (const float*)d_in[3];
    const float* proj_b = (const float*)d_in[4];
    float* out = (float*)d_out;

    cudaFuncSetAttribute(k_qkv_gemm,  cudaFuncAttributeMaxDynamicSharedMemorySize, SMEM_BYTES);
    cudaFuncSetAttribute(k_proj_gemm, cudaFuncAttributeMaxDynamicSharedMemorySize, SMEM_BYTES);

    k_prep<<<131072 + 2048, 128>>>(x, qkv_w, proj_w);
    k_qkv_gemm<<<dim3(12, 1024), 256, SMEM_BYTES>>>(qkv_b);
    k_attn_f16<<<2048 * 8, 128>>>();
    k_proj_gemm<<<dim3(4, 1024), 256, SMEM_BYTES>>>(proj_b, out);
}

// round 12
// speedup vs baseline: 1.9717x; 1.0192x over previous
#include <cuda_runtime.h>
#include <cuda_fp16.h>
#include <cstdint>

// Problem constants:
// B=8, H=W=128, DIM=512, NH=8, HD=64, WIN=8x8 (N=64 tok/window), SHIFT=(4,4)
// windows: 2048 ; rows M = 131072

// Scratch (device globals = sanctioned scratch)
__device__ __half g_qkvh[3u * 2048u * 8u * 64u * 64u]; // [part][win][h][t][d] fp16; q,k RoPE'd
__device__ __half g_xh [131072u * 512u];               // gathered x, fp16
__device__ __half g_oh [131072u * 512u];               // attention out, fp16
__device__ __half g_wqh[1536u * 512u];                 // qkv_w fp16
__device__ __half g_wph[512u * 512u];                  // proj_w fp16

#define L2T16 0.8304820237218406f      // log2(10000)/16

// ---------------------------------------------------------------------------
// helpers
// ---------------------------------------------------------------------------
__device__ __forceinline__ void cp16(uint32_t smem, const void* gmem) {
    asm volatile("cp.async.cg.shared.global [%0], [%1], 16;\n" :: "r"(smem), "l"(gmem));
}
__device__ __forceinline__ void mma_f16(float* c, const uint32_t* a, const uint32_t* b) {
    asm volatile(
        "mma.sync.aligned.m16n8k16.row.col.f32.f16.f16.f32 "
        "{%0,%1,%2,%3}, {%4,%5,%6,%7}, {%8,%9}, {%0,%1,%2,%3};"
        : "+f"(c[0]), "+f"(c[1]), "+f"(c[2]), "+f"(c[3])
        : "r"(a[0]), "r"(a[1]), "r"(a[2]), "r"(a[3]), "r"(b[0]), "r"(b[1]));
}
__device__ __forceinline__ uint32_t pack_h2(float v0, float v1) {
    uint32_t p;
    asm("cvt.rn.f16x2.f32 %0, %1, %2;" : "=r"(p) : "f"(v1), "f"(v0));
    return p;
}
__device__ __forceinline__ void ldsm_x4(uint32_t* d, uint32_t addr) {
    asm volatile("ldmatrix.sync.aligned.m8n8.x4.shared.b16 {%0,%1,%2,%3}, [%4];"
                 : "=r"(d[0]), "=r"(d[1]), "=r"(d[2]), "=r"(d[3]) : "r"(addr));
}

// GEMM smem geometry (BK=64): rows of 64 halves + 16B pad = 144 bytes.
#define ROWB 144
#define STAGE_B (256 * ROWB)            // A(128 rows) + B(128 rows) = 36864 B
#define SMEM_BYTES (3 * STAGE_B)        // 110592 B -> 2 CTAs/SM

// ---------------------------------------------------------------------------
// Kernel 0: prep — gather x (roll+partition) -> g_xh (fp16); weights -> fp16.
// ---------------------------------------------------------------------------
__global__ __launch_bounds__(128) void k_prep(const float* __restrict__ x,
                                              const float* __restrict__ qkv_w,
                                              const float* __restrict__ proj_w)
{
    const int bid = blockIdx.x;
    const int tid = threadIdx.x;

    const float* src;
    __half* dst;
    if (bid < 131072) {
        int m   = bid;
        int win = m >> 6, t = m & 63;
        int b   = win >> 8;
        int wh  = (win >> 4) & 15;
        int ww  = win & 15;
        int i   = t >> 3, j = t & 7;
        int r   = (wh * 8 + i + 4) & 127;     // roll(-4) gather
        int c   = (ww * 8 + j + 4) & 127;
        src = x + ((size_t)((((b << 7) | r) << 7) | c) << 9);
        dst = g_xh + (size_t)m * 512;
    } else {
        int w = bid - 131072;
        if (w < 1536) { src = qkv_w + (size_t)w * 512;           dst = g_wqh + (size_t)w * 512; }
        else          { src = proj_w + (size_t)(w - 1536) * 512; dst = g_wph + (size_t)(w - 1536) * 512; }
    }

    float4 v = ((const float4*)src)[tid];
    uint2 o;
    o.x = pack_h2(v.x, v.y);
    o.y = pack_h2(v.z, v.w);
    ((uint2*)dst)[tid] = o;
}

// ---------------------------------------------------------------------------
// fp16 GEMM core: BM=BN=128, BK=64, K=512 (8 ktiles), 256 threads,
// 8 warps (4M x 2N), warp tile 32x64, m16n8k16, all-x4 ldmatrix fragments,
// 3-stage cp.async, 1 barrier per ktile, fp32 accumulators.
// Per ks-step: 2 ldsm.x4 (A) + 2 ldsm.x4 (B, each covering 2 ni) + 16 mma.
// ---------------------------------------------------------------------------
#define GEMM_MAIN(APTR, BPTR)                                                  \
    const int q_  = lane >> 3, r_ = lane & 7;                                  \
    uint32_t aLane[2];                                                         \
    _Pragma("unroll")                                                          \
    for (int mi = 0; mi < 2; mi++)                                             \
        aLane[mi] = (uint32_t)((warpM * 32 + mi * 16 + (q_ & 1) * 8 + r_) * ROWB \
                               + (q_ >> 1) * 16);                              \
    /* B x4: lanes 0-7 -> (rows nb+r, +0B), 8-15 -> (+16B), 16-23 -> rows+8,  */\
    /* 24-31 -> rows+8,+16B. Covers 2 ni (16 n-rows) per ldsm.               */\
    const uint32_t bLane = (uint32_t)(128 * ROWB +                             \
        (warpN * 64 + ((lane >> 4) << 3) + r_) * ROWB + ((q_ & 1) * 16));      \
    auto loadStage = [&](int s, int k0) {                                      \
        uint32_t ab = smemBase + s * STAGE_B;                                  \
        uint32_t bb = ab + 128 * ROWB;                                         \
        _Pragma("unroll")                                                      \
        for (int it = 0; it < 4; it++) {                                       \
            int ch = tid + it * 256;          /* 0..1023 */                    \
            int row = ch >> 3, ci = ch & 7;                                    \
            cp16(ab + row * ROWB + ci * 16, APTR + (size_t)row * 512 + k0 + ci * 8); \
            cp16(bb + row * ROWB + ci * 16, BPTR + (size_t)row * 512 + k0 + ci * 8); \
        }                                                                      \
    };                                                                         \
    loadStage(0, 0);                                                           \
    asm volatile("cp.async.commit_group;\n");                                  \
    loadStage(1, 64);                                                          \
    asm volatile("cp.async.commit_group;\n");                                  \
    asm volatile("cp.async.wait_group 1;\n");                                  \
    __syncthreads();                                                           \
    int ldS = 2, cpS = 0;                                                      \
    for (int kt = 0; kt < 8; kt++) {                                           \
        if (kt + 2 < 8) {                                                      \
            loadStage(ldS, (kt + 2) * 64);                                     \
            asm volatile("cp.async.commit_group;\n");                          \
            if (++ldS == 3) ldS = 0;                                           \
        }                                                                      \
        const uint32_t stA = smemBase + cpS * STAGE_B;                         \
        _Pragma("unroll")                                                      \
        for (int ks = 0; ks < 4; ks++) {                                       \
            uint32_t af[2][4];                                                 \
            ldsm_x4(af[0], stA + aLane[0] + ks * 32);                          \
            ldsm_x4(af[1], stA + aLane[1] + ks * 32);                          \
            _Pragma("unroll")                                                  \
            for (int ni2 = 0; ni2 < 4; ni2++) {                                \
                uint32_t bf[4];                                                \
                ldsm_x4(bf, stA + bLane + ni2 * (16 * ROWB) + ks * 32);        \
                mma_f16(acc[0][ni2 * 2 + 0], af[0], bf);                       \
                mma_f16(acc[1][ni2 * 2 + 0], af[1], bf);                       \
                mma_f16(acc[0][ni2 * 2 + 1], af[0], bf + 2);                   \
                mma_f16(acc[1][ni2 * 2 + 1], af[1], bf + 2);                   \
            }                                                                  \
        }                                                                      \
        if (++cpS == 3) cpS = 0;                                               \
        if (kt < 7) {                                                          \
            if (kt + 2 < 8) asm volatile("cp.async.wait_group 1;\n");          \
            else            asm volatile("cp.async.wait_group 0;\n");          \
            __syncthreads();                                                   \
        }                                                                      \
    }

// ---------------------------------------------------------------------------
// Kernel 1: QKV GEMM (fp16) + bias + fused RoPE/scale + fp16 pack -> g_qkvh.
//   M=131072 K=512 N=1536
// ---------------------------------------------------------------------------
__global__ __launch_bounds__(256, 2) void k_qkv_gemm(const float* __restrict__ bias)
{
    extern __shared__ uint32_t sm32[];
    const uint32_t smemBase = (uint32_t)__cvta_generic_to_shared(sm32);

    const int tid   = threadIdx.x;
    const int nTile = blockIdx.x;
    const int mTile = blockIdx.y;

    const int warpId = tid >> 5, lane = tid & 31;
    const int warpM  = warpId & 3;
    const int warpN  = warpId >> 2;
    const int n0     = nTile * 128;
    const int g      = lane >> 2, t4 = lane & 3;

    float acc[2][8][4];
#pragma unroll
    for (int mi = 0; mi < 2; mi++)
#pragma unroll
        for (int ni = 0; ni < 8; ni++)
#pragma unroll
            for (int e = 0; e < 4; e++) acc[mi][ni][e] = 0.f;

    const __half* Ag = g_xh + (size_t)(mTile * 128) * 512;
    const __half* Bg = g_wqh + (size_t)n0 * 512;
    GEMM_MAIN(Ag, Bg)

    const int nbase = n0 + warpN * 64;     // 64-aligned -> one (part, head)
    const int part  = nbase >> 9;
    const int h     = (nbase >> 6) & 7;

    // bias (reference: GEMM + b, THEN rope)
#pragma unroll
    for (int ni = 0; ni < 8; ni++) {
        int n = nbase + ni * 8 + 2 * t4;
        float b0 = bias[n], b1 = bias[n + 1];
#pragma unroll
        for (int mi = 0; mi < 2; mi++) {
            acc[mi][ni][0] += b0; acc[mi][ni][1] += b1;
            acc[mi][ni][2] += b0; acc[mi][ni][3] += b1;
        }
    }

    if (part < 2) {
        const float scale = (part == 0) ? 0.125f : 1.0f;
        float invv[2][2];  // [ni&1][j]: e = (ni&1)*8 + 2*t4 + j
#pragma unroll
        for (int p = 0; p < 2; p++)
#pragma unroll
            for (int j = 0; j < 2; j++)
                invv[p][j] = exp2f(-(float)(p * 8 + 2 * t4 + j) * L2T16);

#pragma unroll
        for (int mi = 0; mi < 2; mi++) {
#pragma unroll
            for (int rr = 0; rr < 2; rr++) {
                int t = (mTile * 128 + warpM * 32 + mi * 16 + g + rr * 8) & 63;
                float posR = (float)(t >> 3), posC = (float)(t & 7);
#pragma unroll
                for (int qq = 0; qq < 4; qq++) {
                    const int niList[4] = {0, 1, 4, 5};
                    int ni = niList[qq];
                    float pos = (ni < 4) ? posR : posC;
#pragma unroll
                    for (int j = 0; j < 2; j++) {
                        float ang = pos * invv[ni & 1][j];
                        float sv, cv;
                        __sincosf(ang, &sv, &cv);
                        float a = acc[mi][ni][rr * 2 + j];
                        float b = acc[mi][ni + 2][rr * 2 + j];
                        acc[mi][ni][rr * 2 + j]     = (a * cv - b * sv) * scale;
                        acc[mi][ni + 2][rr * 2 + j] = (b * cv + a * sv) * scale;
                    }
                }
            }
        }
    }

    // pack fp16 + scatter into g_qkvh[part][win][h][t][d]
    uint32_t* gq = (uint32_t*)g_qkvh;
#pragma unroll
    for (int ni = 0; ni < 8; ni++) {
        int d0 = ni * 8 + 2 * t4;          // even
#pragma unroll
        for (int mi = 0; mi < 2; mi++) {
#pragma unroll
            for (int rr = 0; rr < 2; rr++) {
                int m   = mTile * 128 + warpM * 32 + mi * 16 + g + rr * 8;
                int win = m >> 6, t = m & 63;
                size_t idx = ((((size_t)part * 2048 + win) * 8 + h) * 64 + t) * 64 + d0;
                gq[idx >> 1] = pack_h2(acc[mi][ni][rr * 2 + 0], acc[mi][ni][rr * 2 + 1]);
            }
        }
    }
}

// ---------------------------------------------------------------------------
// Kernel 2: per (window, head) attention, all-fp16 MMA (fp32 accum/softmax).
// 128 threads; warp w owns rows [16w,16w+16). ONE __syncthreads total.
// ---------------------------------------------------------------------------
#define ASTW 36   // words per 64-half row (32 data + 4 pad)

__global__ __launch_bounds__(128) void k_attn_f16()
{
    __shared__ uint32_t Qs[64 * ASTW];   // Q [t][d]; P overlays own strip
    __shared__ uint32_t Ks[64 * ASTW];   // K [t][d]
    __shared__ uint32_t Vs[64 * ASTW];   // V [d][t] (transposed at load)

    const int tid  = threadIdx.x;
    const int warp = tid >> 5;
    const int lane = tid & 31;
    const int g    = lane >> 2;
    const int c    = lane & 3;
    const int m0   = warp * 16;

    const int win = blockIdx.x >> 3;
    const int h   = blockIdx.x & 7;

    const size_t qoff = ((size_t)win * 8 + h) * 4096;
    const size_t pstr = (size_t)2048 * 8 * 4096;
    const uint4* qg = (const uint4*)(g_qkvh + qoff);
    const uint4* kg = (const uint4*)(g_qkvh + pstr + qoff);
    const uint4* vg = (const uint4*)(g_qkvh + 2 * pstr + qoff);
    __half* VsH = (__half*)Vs;

#pragma unroll
    for (int it = 0; it < 4; it++) {
        int e4 = tid + it * 128;
        int t  = e4 >> 3;
        int ci = e4 & 7;
        *(uint4*)(Qs + t * ASTW + ci * 4) = qg[e4];
        *(uint4*)(Ks + t * ASTW + ci * 4) = kg[e4];
        uint4 w = vg[e4];
        const __half* hb = (const __half*)&w;
#pragma unroll
        for (int k = 0; k < 8; k++)
            VsH[(ci * 8 + k) * (2 * ASTW) + t] = hb[k];
    }
    __syncthreads();

    uint32_t areg[4][4];
#pragma unroll
    for (int ks = 0; ks < 4; ks++) {
        const uint32_t* ap = Qs + (m0 + g) * ASTW + ks * 8 + c;
        areg[ks][0] = ap[0];
        areg[ks][1] = ap[8 * ASTW];
        areg[ks][2] = ap[4];
        areg[ks][3] = ap[8 * ASTW + 4];
    }

    float sacc[8][4];
#pragma unroll
    for (int ni = 0; ni < 8; ni++)
#pragma unroll
        for (int e = 0; e < 4; e++) sacc[ni][e] = 0.f;

#pragma unroll
    for (int ni = 0; ni < 8; ni++) {
        const uint32_t* bb = Ks + (ni * 8 + g) * ASTW + c;
#pragma unroll
        for (int ks = 0; ks < 4; ks++) {
            uint32_t bf[2] = { bb[ks * 8], bb[ks * 8 + 4] };
            mma_f16(sacc[ni], areg[ks], bf);
        }
    }

    const bool maskOn = (((win >> 4) & 15) == 15);
    const bool warpLo = (warp < 2);

    float mx1 = -1e30f, mx2 = -1e30f;
#pragma unroll
    for (int ni = 0; ni < 8; ni++) {
        float msub = (maskOn && ((ni < 4) != warpLo)) ? 100.f : 0.f;
        sacc[ni][0] -= msub; sacc[ni][1] -= msub;
        sacc[ni][2] -= msub; sacc[ni][3] -= msub;
        mx1 = fmaxf(mx1, fmaxf(sacc[ni][0], sacc[ni][1]));
        mx2 = fmaxf(mx2, fmaxf(sacc[ni][2], sacc[ni][3]));
    }
    mx1 = fmaxf(mx1, __shfl_xor_sync(0xffffffffu, mx1, 1));
    mx1 = fmaxf(mx1, __shfl_xor_sync(0xffffffffu, mx1, 2));
    mx2 = fmaxf(mx2, __shfl_xor_sync(0xffffffffu, mx2, 1));
    mx2 = fmaxf(mx2, __shfl_xor_sync(0xffffffffu, mx2, 2));

    float s1 = 0.f, s2 = 0.f;
#pragma unroll
    for (int ni = 0; ni < 8; ni++) {
        sacc[ni][0] = __expf(sacc[ni][0] - mx1);
        sacc[ni][1] = __expf(sacc[ni][1] - mx1);
        sacc[ni][2] = __expf(sacc[ni][2] - mx2);
        sacc[ni][3] = __expf(sacc[ni][3] - mx2);
        s1 += sacc[ni][0] + sacc[ni][1];
        s2 += sacc[ni][2] + sacc[ni][3];
    }
    s1 += __shfl_xor_sync(0xffffffffu, s1, 1);
    s1 += __shfl_xor_sync(0xffffffffu, s1, 2);
    s2 += __shfl_xor_sync(0xffffffffu, s2, 1);
    s2 += __shfl_xor_sync(0xffffffffu, s2, 2);
    const float i1 = 1.f / s1, i2 = 1.f / s2;

#pragma unroll
    for (int ni = 0; ni < 8; ni++) {
        Qs[(m0 + g) * ASTW + ni * 4 + c]     = pack_h2(sacc[ni][0] * i1, sacc[ni][1] * i1);
        Qs[(m0 + g + 8) * ASTW + ni * 4 + c] = pack_h2(sacc[ni][2] * i2, sacc[ni][3] * i2);
    }
    __syncwarp();

    uint32_t preg[4][4];
#pragma unroll
    for (int ks = 0; ks < 4; ks++) {
        const uint32_t* pp = Qs + (m0 + g) * ASTW + ks * 8 + c;
        preg[ks][0] = pp[0];
        preg[ks][1] = pp[8 * ASTW];
        preg[ks][2] = pp[4];
        preg[ks][3] = pp[8 * ASTW + 4];
    }

    float oacc[8][4];
#pragma unroll
    for (int ni = 0; ni < 8; ni++)
#pragma unroll
        for (int e = 0; e < 4; e++) oacc[ni][e] = 0.f;

#pragma unroll
    for (int ni = 0; ni < 8; ni++) {
        const uint32_t* bb = Vs + (ni * 8 + g) * ASTW + c;
#pragma unroll
        for (int ks = 0; ks < 4; ks++) {
            uint32_t bf[2] = { bb[ks * 8], bb[ks * 8 + 4] };
            mma_f16(oacc[ni], preg[ks], bf);
        }
    }

    uint32_t* goh = (uint32_t*)g_oh;
    const size_t mrow1 = (size_t)win * 64 + m0 + g;
    const size_t mrow2 = mrow1 + 8;
#pragma unroll
    for (int ni = 0; ni < 8; ni++) {
        int d0 = h * 64 + ni * 8 + 2 * c;
        goh[(mrow1 * 512 + d0) >> 1] = pack_h2(oacc[ni][0], oacc[ni][1]);
        goh[(mrow2 * 512 + d0) >> 1] = pack_h2(oacc[ni][2], oacc[ni][3]);
    }
}

// ---------------------------------------------------------------------------
// Kernel 3: proj GEMM (fp16) + bias + unpartition/roll scatter.
//   M=131072 K=512 N=512
// ---------------------------------------------------------------------------
__global__ __launch_bounds__(256, 2) void k_proj_gemm(const float* __restrict__ bias,
                                                      float* __restrict__ out)
{
    extern __shared__ uint32_t sm32[];
    const uint32_t smemBase = (uint32_t)__cvta_generic_to_shared(sm32);

    const int tid   = threadIdx.x;
    const int nTile = blockIdx.x;
    const int mTile = blockIdx.y;

    const int warpId = tid >> 5, lane = tid & 31;
    const int warpM  = warpId & 3;
    const int warpN  = warpId >> 2;
    const int n0     = nTile * 128;
    const int g      = lane >> 2, t4 = lane & 3;

    float acc[2][8][4];
#pragma unroll
    for (int mi = 0; mi < 2; mi++)
#pragma unroll
        for (int ni = 0; ni < 8; ni++)
#pragma unroll
            for (int e = 0; e < 4; e++) acc[mi][ni][e] = 0.f;

    const __half* Ag = g_oh + (size_t)(mTile * 128) * 512;
    const __half* Bg = g_wph + (size_t)n0 * 512;
    GEMM_MAIN(Ag, Bg)

#pragma unroll
    for (int ni = 0; ni < 8; ni++) {
        int n  = n0 + warpN * 64 + ni * 8 + 2 * t4;
        float b0 = bias[n], b1 = bias[n + 1];
#pragma unroll
        for (int mi = 0; mi < 2; mi++) {
#pragma unroll
            for (int rr2 = 0; rr2 < 2; rr2++) {
                int m   = mTile * 128 + warpM * 32 + mi * 16 + g + rr2 * 8;
                int win = m >> 6, tt = m & 63;
                int b   = win >> 8;
                int wh  = (win >> 4) & 15;
                int ww  = win & 15;
                int ii  = tt >> 3, jj = tt & 7;
                int rO  = (wh * 8 + ii + 4) & 127;
                int cO  = (ww * 8 + jj + 4) & 127;
                size_t off = ((((size_t)b << 7) | rO) << 7 | cO) << 9;
                float2 v = make_float2(acc[mi][ni][rr2 * 2 + 0] + b0,
                                       acc[mi][ni][rr2 * 2 + 1] + b1);
                *(float2*)(out + off + n) = v;
            }
        }
    }
}

// ---------------------------------------------------------------------------
extern "C" void kernel_launch(void* const* d_in, const int* in_sizes, int n_in,
                              void* d_out, int out_size)
{
    const float* x      = (const float*)d_in[0];
    const float* qkv_w  = (const float*)d_in[1];
    const float* qkv_b  = (const float*)d_in[2];
    const float* proj_w = (const float*)d_in[3];
    const float* proj_b = (const float*)d_in[4];
    float* out = (float*)d_out;

    cudaFuncSetAttribute(k_qkv_gemm,  cudaFuncAttributeMaxDynamicSharedMemorySize, SMEM_BYTES);
    cudaFuncSetAttribute(k_proj_gemm, cudaFuncAttributeMaxDynamicSharedMemorySize, SMEM_BYTES);

    k_prep<<<131072 + 2048, 128>>>(x, qkv_w, proj_w);
    k_qkv_gemm<<<dim3(12, 1024), 256, SMEM_BYTES>>>(qkv_b);
    k_attn_f16<<<2048 * 8, 128>>>();
    k_proj_gemm<<<dim3(4, 1024), 256, SMEM_BYTES>>>(proj_b, out);
}

// round 13
// speedup vs baseline: 1.9878x; 1.0082x over previous
#include <cuda_runtime.h>
#include <cuda_fp16.h>
#include <cstdint>

// Problem constants:
// B=8, H=W=128, DIM=512, NH=8, HD=64, WIN=8x8 (N=64 tok/window), SHIFT=(4,4)
// windows: 2048 ; rows M = 131072

// Scratch (device globals = sanctioned scratch)
__device__ __half g_qkvh[3u * 2048u * 8u * 64u * 64u]; // [part][win][h][t][d] fp16; q,k RoPE'd
__device__ __half g_xh [131072u * 512u];               // gathered x, fp16
__device__ __half g_oh [131072u * 512u];               // attention out, fp16
__device__ __half g_wqh[1536u * 512u];                 // qkv_w fp16
__device__ __half g_wph[512u * 512u];                  // proj_w fp16

#define L2T16 0.8304820237218406f      // log2(10000)/16

// ---------------------------------------------------------------------------
// helpers
// ---------------------------------------------------------------------------
__device__ __forceinline__ void cp16(uint32_t smem, const void* gmem) {
    asm volatile("cp.async.cg.shared.global [%0], [%1], 16;\n" :: "r"(smem), "l"(gmem));
}
__device__ __forceinline__ void mma_f16(float* c, const uint32_t* a, const uint32_t* b) {
    asm volatile(
        "mma.sync.aligned.m16n8k16.row.col.f32.f16.f16.f32 "
        "{%0,%1,%2,%3}, {%4,%5,%6,%7}, {%8,%9}, {%0,%1,%2,%3};"
        : "+f"(c[0]), "+f"(c[1]), "+f"(c[2]), "+f"(c[3])
        : "r"(a[0]), "r"(a[1]), "r"(a[2]), "r"(a[3]), "r"(b[0]), "r"(b[1]));
}
__device__ __forceinline__ uint32_t pack_h2(float v0, float v1) {
    uint32_t p;
    asm("cvt.rn.f16x2.f32 %0, %1, %2;" : "=r"(p) : "f"(v1), "f"(v0));
    return p;
}
__device__ __forceinline__ void ldsm_x4(uint32_t* d, uint32_t addr) {
    asm volatile("ldmatrix.sync.aligned.m8n8.x4.shared.b16 {%0,%1,%2,%3}, [%4];"
                 : "=r"(d[0]), "=r"(d[1]), "=r"(d[2]), "=r"(d[3]) : "r"(addr));
}

// GEMM smem geometry (BK=64): rows of 64 halves + 16B pad = 144 bytes.
#define ROWB 144
#define STAGE_B (256 * ROWB)            // A(128 rows) + B(128 rows) = 36864 B
#define SMEM_BYTES (3 * STAGE_B)        // 110592 B -> 2 CTAs/SM

// ---------------------------------------------------------------------------
// Kernel 0: prep — gather x (roll+partition) -> g_xh (fp16); weights -> fp16.
// Coarsened: 4 rows per CTA, 128 threads, fully coalesced.
// ---------------------------------------------------------------------------
__global__ __launch_bounds__(128) void k_prep(const float* __restrict__ x,
                                              const float* __restrict__ qkv_w,
                                              const float* __restrict__ proj_w)
{
    const int bid = blockIdx.x;
    const int tid = threadIdx.x;

#pragma unroll
    for (int it = 0; it < 4; it++) {
        int e   = tid + it * 128;       // 0..511
        int rl  = e >> 7;               // row within CTA group (0..3)
        int f4  = e & 127;              // float4 index within row

        const float* src;
        __half* dst;
        if (bid < 32768) {
            int m   = bid * 4 + rl;
            int win = m >> 6, t = m & 63;
            int b   = win >> 8;
            int wh  = (win >> 4) & 15;
            int ww  = win & 15;
            int i   = t >> 3, j = t & 7;
            int r   = (wh * 8 + i + 4) & 127;     // roll(-4) gather
            int c   = (ww * 8 + j + 4) & 127;
            src = x + ((size_t)((((b << 7) | r) << 7) | c) << 9);
            dst = g_xh + (size_t)m * 512;
        } else {
            int w = (bid - 32768) * 4 + rl;        // 0..2047
            if (w < 1536) { src = qkv_w + (size_t)w * 512;           dst = g_wqh + (size_t)w * 512; }
            else          { src = proj_w + (size_t)(w - 1536) * 512; dst = g_wph + (size_t)(w - 1536) * 512; }
        }

        float4 v = ((const float4*)src)[f4];
        uint2 o;
        o.x = pack_h2(v.x, v.y);
        o.y = pack_h2(v.z, v.w);
        ((uint2*)dst)[f4] = o;
    }
}

// ---------------------------------------------------------------------------
// fp16 GEMM core: BM=BN=128, BK=64, K=512 (8 ktiles), 256 threads,
// 8 warps (4M x 2N), warp tile 32x64, m16n8k16.
// A fragments for the WHOLE ktile hoisted before the ks loop (removes the
// per-ks A-ldsm -> MMA dependency chain). 3-stage cp.async, 1 barrier/ktile.
// ---------------------------------------------------------------------------
#define GEMM_MAIN(APTR, BPTR)                                                  \
    const int q_  = lane >> 3, r_ = lane & 7;                                  \
    uint32_t aLane[2];                                                         \
    _Pragma("unroll")                                                          \
    for (int mi = 0; mi < 2; mi++)                                             \
        aLane[mi] = (uint32_t)((warpM * 32 + mi * 16 + (q_ & 1) * 8 + r_) * ROWB \
                               + (q_ >> 1) * 16);                              \
    const uint32_t bLane = (uint32_t)(128 * ROWB +                             \
        (warpN * 64 + ((lane >> 4) << 3) + r_) * ROWB + ((q_ & 1) * 16));      \
    auto loadStage = [&](int s, int k0) {                                      \
        uint32_t ab = smemBase + s * STAGE_B;                                  \
        uint32_t bb = ab + 128 * ROWB;                                         \
        _Pragma("unroll")                                                      \
        for (int it = 0; it < 4; it++) {                                       \
            int ch = tid + it * 256;          /* 0..1023 */                    \
            int row = ch >> 3, ci = ch & 7;                                    \
            cp16(ab + row * ROWB + ci * 16, APTR + (size_t)row * 512 + k0 + ci * 8); \
            cp16(bb + row * ROWB + ci * 16, BPTR + (size_t)row * 512 + k0 + ci * 8); \
        }                                                                      \
    };                                                                         \
    loadStage(0, 0);                                                           \
    asm volatile("cp.async.commit_group;\n");                                  \
    loadStage(1, 64);                                                          \
    asm volatile("cp.async.commit_group;\n");                                  \
    asm volatile("cp.async.wait_group 1;\n");                                  \
    __syncthreads();                                                           \
    int ldS = 2, cpS = 0;                                                      \
    for (int kt = 0; kt < 8; kt++) {                                           \
        if (kt + 2 < 8) {                                                      \
            loadStage(ldS, (kt + 2) * 64);                                     \
            asm volatile("cp.async.commit_group;\n");                          \
            if (++ldS == 3) ldS = 0;                                           \
        }                                                                      \
        const uint32_t stA = smemBase + cpS * STAGE_B;                         \
        uint32_t af[4][2][4];                                                  \
        _Pragma("unroll")                                                      \
        for (int ks = 0; ks < 4; ks++) {                                       \
            ldsm_x4(af[ks][0], stA + aLane[0] + ks * 32);                      \
            ldsm_x4(af[ks][1], stA + aLane[1] + ks * 32);                      \
        }                                                                      \
        _Pragma("unroll")                                                      \
        for (int ks = 0; ks < 4; ks++) {                                       \
            _Pragma("unroll")                                                  \
            for (int ni2 = 0; ni2 < 4; ni2++) {                                \
                uint32_t bf[4];                                                \
                ldsm_x4(bf, stA + bLane + ni2 * (16 * ROWB) + ks * 32);        \
                mma_f16(acc[0][ni2 * 2 + 0], af[ks][0], bf);                   \
                mma_f16(acc[1][ni2 * 2 + 0], af[ks][1], bf);                   \
                mma_f16(acc[0][ni2 * 2 + 1], af[ks][0], bf + 2);               \
                mma_f16(acc[1][ni2 * 2 + 1], af[ks][1], bf + 2);               \
            }                                                                  \
        }                                                                      \
        if (++cpS == 3) cpS = 0;                                               \
        if (kt < 7) {                                                          \
            if (kt + 2 < 8) asm volatile("cp.async.wait_group 1;\n");          \
            else            asm volatile("cp.async.wait_group 0;\n");          \
            __syncthreads();                                                   \
        }                                                                      \
    }

// ---------------------------------------------------------------------------
// Kernel 1: QKV GEMM (fp16) + bias + fused RoPE/scale + fp16 pack -> g_qkvh.
//   M=131072 K=512 N=1536
// ---------------------------------------------------------------------------
__global__ __launch_bounds__(256, 2) void k_qkv_gemm(const float* __restrict__ bias)
{
    extern __shared__ uint32_t sm32[];
    const uint32_t smemBase = (uint32_t)__cvta_generic_to_shared(sm32);

    const int tid   = threadIdx.x;
    const int nTile = blockIdx.x;
    const int mTile = blockIdx.y;

    const int warpId = tid >> 5, lane = tid & 31;
    const int warpM  = warpId & 3;
    const int warpN  = warpId >> 2;
    const int n0     = nTile * 128;
    const int g      = lane >> 2, t4 = lane & 3;

    float acc[2][8][4];
#pragma unroll
    for (int mi = 0; mi < 2; mi++)
#pragma unroll
        for (int ni = 0; ni < 8; ni++)
#pragma unroll
            for (int e = 0; e < 4; e++) acc[mi][ni][e] = 0.f;

    const __half* Ag = g_xh + (size_t)(mTile * 128) * 512;
    const __half* Bg = g_wqh + (size_t)n0 * 512;
    GEMM_MAIN(Ag, Bg)

    const int nbase = n0 + warpN * 64;     // 64-aligned -> one (part, head)
    const int part  = nbase >> 9;
    const int h     = (nbase >> 6) & 7;

    // bias (reference: GEMM + b, THEN rope)
#pragma unroll
    for (int ni = 0; ni < 8; ni++) {
        int n = nbase + ni * 8 + 2 * t4;
        float b0 = bias[n], b1 = bias[n + 1];
#pragma unroll
        for (int mi = 0; mi < 2; mi++) {
            acc[mi][ni][0] += b0; acc[mi][ni][1] += b1;
            acc[mi][ni][2] += b0; acc[mi][ni][3] += b1;
        }
    }

    if (part < 2) {
        const float scale = (part == 0) ? 0.125f : 1.0f;
        float invv[2][2];  // [ni&1][j]: e = (ni&1)*8 + 2*t4 + j
#pragma unroll
        for (int p = 0; p < 2; p++)
#pragma unroll
            for (int j = 0; j < 2; j++)
                invv[p][j] = exp2f(-(float)(p * 8 + 2 * t4 + j) * L2T16);

#pragma unroll
        for (int mi = 0; mi < 2; mi++) {
#pragma unroll
            for (int rr = 0; rr < 2; rr++) {
                int t = (mTile * 128 + warpM * 32 + mi * 16 + g + rr * 8) & 63;
                float posR = (float)(t >> 3), posC = (float)(t & 7);
#pragma unroll
                for (int qq = 0; qq < 4; qq++) {
                    const int niList[4] = {0, 1, 4, 5};
                    int ni = niList[qq];
                    float pos = (ni < 4) ? posR : posC;
#pragma unroll
                    for (int j = 0; j < 2; j++) {
                        float ang = pos * invv[ni & 1][j];
                        float sv, cv;
                        __sincosf(ang, &sv, &cv);
                        float a = acc[mi][ni][rr * 2 + j];
                        float b = acc[mi][ni + 2][rr * 2 + j];
                        acc[mi][ni][rr * 2 + j]     = (a * cv - b * sv) * scale;
                        acc[mi][ni + 2][rr * 2 + j] = (b * cv + a * sv) * scale;
                    }
                }
            }
        }
    }

    // pack fp16 + scatter into g_qkvh[part][win][h][t][d]
    uint32_t* gq = (uint32_t*)g_qkvh;
#pragma unroll
    for (int ni = 0; ni < 8; ni++) {
        int d0 = ni * 8 + 2 * t4;          // even
#pragma unroll
        for (int mi = 0; mi < 2; mi++) {
#pragma unroll
            for (int rr = 0; rr < 2; rr++) {
                int m   = mTile * 128 + warpM * 32 + mi * 16 + g + rr * 8;
                int win = m >> 6, t = m & 63;
                size_t idx = ((((size_t)part * 2048 + win) * 8 + h) * 64 + t) * 64 + d0;
                gq[idx >> 1] = pack_h2(acc[mi][ni][rr * 2 + 0], acc[mi][ni][rr * 2 + 1]);
            }
        }
    }
}

// ---------------------------------------------------------------------------
// Kernel 2: per (window, head) attention, all-fp16 MMA (fp32 accum/softmax).
// 128 threads; warp w owns rows [16w,16w+16). ONE __syncthreads total.
// ---------------------------------------------------------------------------
#define ASTW 36   // words per 64-half row (32 data + 4 pad)

__global__ __launch_bounds__(128) void k_attn_f16()
{
    __shared__ uint32_t Qs[64 * ASTW];   // Q [t][d]; P overlays own strip
    __shared__ uint32_t Ks[64 * ASTW];   // K [t][d]
    __shared__ uint32_t Vs[64 * ASTW];   // V [d][t] (transposed at load)

    const int tid  = threadIdx.x;
    const int warp = tid >> 5;
    const int lane = tid & 31;
    const int g    = lane >> 2;
    const int c    = lane & 3;
    const int m0   = warp * 16;

    const int win = blockIdx.x >> 3;
    const int h   = blockIdx.x & 7;

    const size_t qoff = ((size_t)win * 8 + h) * 4096;
    const size_t pstr = (size_t)2048 * 8 * 4096;
    const uint4* qg = (const uint4*)(g_qkvh + qoff);
    const uint4* kg = (const uint4*)(g_qkvh + pstr + qoff);
    const uint4* vg = (const uint4*)(g_qkvh + 2 * pstr + qoff);
    __half* VsH = (__half*)Vs;

#pragma unroll
    for (int it = 0; it < 4; it++) {
        int e4 = tid + it * 128;
        int t  = e4 >> 3;
        int ci = e4 & 7;
        *(uint4*)(Qs + t * ASTW + ci * 4) = qg[e4];
        *(uint4*)(Ks + t * ASTW + ci * 4) = kg[e4];
        uint4 w = vg[e4];
        const __half* hb = (const __half*)&w;
#pragma unroll
        for (int k = 0; k < 8; k++)
            VsH[(ci * 8 + k) * (2 * ASTW) + t] = hb[k];
    }
    __syncthreads();

    uint32_t areg[4][4];
#pragma unroll
    for (int ks = 0; ks < 4; ks++) {
        const uint32_t* ap = Qs + (m0 + g) * ASTW + ks * 8 + c;
        areg[ks][0] = ap[0];
        areg[ks][1] = ap[8 * ASTW];
        areg[ks][2] = ap[4];
        areg[ks][3] = ap[8 * ASTW + 4];
    }

    float sacc[8][4];
#pragma unroll
    for (int ni = 0; ni < 8; ni++)
#pragma unroll
        for (int e = 0; e < 4; e++) sacc[ni][e] = 0.f;

#pragma unroll
    for (int ni = 0; ni < 8; ni++) {
        const uint32_t* bb = Ks + (ni * 8 + g) * ASTW + c;
#pragma unroll
        for (int ks = 0; ks < 4; ks++) {
            uint32_t bf[2] = { bb[ks * 8], bb[ks * 8 + 4] };
            mma_f16(sacc[ni], areg[ks], bf);
        }
    }

    const bool maskOn = (((win >> 4) & 15) == 15);
    const bool warpLo = (warp < 2);

    float mx1 = -1e30f, mx2 = -1e30f;
#pragma unroll
    for (int ni = 0; ni < 8; ni++) {
        float msub = (maskOn && ((ni < 4) != warpLo)) ? 100.f : 0.f;
        sacc[ni][0] -= msub; sacc[ni][1] -= msub;
        sacc[ni][2] -= msub; sacc[ni][3] -= msub;
        mx1 = fmaxf(mx1, fmaxf(sacc[ni][0], sacc[ni][1]));
        mx2 = fmaxf(mx2, fmaxf(sacc[ni][2], sacc[ni][3]));
    }
    mx1 = fmaxf(mx1, __shfl_xor_sync(0xffffffffu, mx1, 1));
    mx1 = fmaxf(mx1, __shfl_xor_sync(0xffffffffu, mx1, 2));
    mx2 = fmaxf(mx2, __shfl_xor_sync(0xffffffffu, mx2, 1));
    mx2 = fmaxf(mx2, __shfl_xor_sync(0xffffffffu, mx2, 2));

    float s1 = 0.f, s2 = 0.f;
#pragma unroll
    for (int ni = 0; ni < 8; ni++) {
        sacc[ni][0] = __expf(sacc[ni][0] - mx1);
        sacc[ni][1] = __expf(sacc[ni][1] - mx1);
        sacc[ni][2] = __expf(sacc[ni][2] - mx2);
        sacc[ni][3] = __expf(sacc[ni][3] - mx2);
        s1 += sacc[ni][0] + sacc[ni][1];
        s2 += sacc[ni][2] + sacc[ni][3];
    }
    s1 += __shfl_xor_sync(0xffffffffu, s1, 1);
    s1 += __shfl_xor_sync(0xffffffffu, s1, 2);
    s2 += __shfl_xor_sync(0xffffffffu, s2, 1);
    s2 += __shfl_xor_sync(0xffffffffu, s2, 2);
    const float i1 = 1.f / s1, i2 = 1.f / s2;

#pragma unroll
    for (int ni = 0; ni < 8; ni++) {
        Qs[(m0 + g) * ASTW + ni * 4 + c]     = pack_h2(sacc[ni][0] * i1, sacc[ni][1] * i1);
        Qs[(m0 + g + 8) * ASTW + ni * 4 + c] = pack_h2(sacc[ni][2] * i2, sacc[ni][3] * i2);
    }
    __syncwarp();

    uint32_t preg[4][4];
#pragma unroll
    for (int ks = 0; ks < 4; ks++) {
        const uint32_t* pp = Qs + (m0 + g) * ASTW + ks * 8 + c;
        preg[ks][0] = pp[0];
        preg[ks][1] = pp[8 * ASTW];
        preg[ks][2] = pp[4];
        preg[ks][3] = pp[8 * ASTW + 4];
    }

    float oacc[8][4];
#pragma unroll
    for (int ni = 0; ni < 8; ni++)
#pragma unroll
        for (int e = 0; e < 4; e++) oacc[ni][e] = 0.f;

#pragma unroll
    for (int ni = 0; ni < 8; ni++) {
        const uint32_t* bb = Vs + (ni * 8 + g) * ASTW + c;
#pragma unroll
        for (int ks = 0; ks < 4; ks++) {
            uint32_t bf[2] = { bb[ks * 8], bb[ks * 8 + 4] };
            mma_f16(oacc[ni], preg[ks], bf);
        }
    }

    uint32_t* goh = (uint32_t*)g_oh;
    const size_t mrow1 = (size_t)win * 64 + m0 + g;
    const size_t mrow2 = mrow1 + 8;
#pragma unroll
    for (int ni = 0; ni < 8; ni++) {
        int d0 = h * 64 + ni * 8 + 2 * c;
        goh[(mrow1 * 512 + d0) >> 1] = pack_h2(oacc[ni][0], oacc[ni][1]);
        goh[(mrow2 * 512 + d0) >> 1] = pack_h2(oacc[ni][2], oacc[ni][3]);
    }
}

// ---------------------------------------------------------------------------
// Kernel 3: proj GEMM (fp16) + bias + unpartition/roll scatter.
//   M=131072 K=512 N=512
// ---------------------------------------------------------------------------
__global__ __launch_bounds__(256, 2) void k_proj_gemm(const float* __restrict__ bias,
                                                      float* __restrict__ out)
{
    extern __shared__ uint32_t sm32[];
    const uint32_t smemBase = (uint32_t)__cvta_generic_to_shared(sm32);

    const int tid   = threadIdx.x;
    const int nTile = blockIdx.x;
    const int mTile = blockIdx.y;

    const int warpId = tid >> 5, lane = tid & 31;
    const int warpM  = warpId & 3;
    const int warpN  = warpId >> 2;
    const int n0     = nTile * 128;
    const int g      = lane >> 2, t4 = lane & 3;

    float acc[2][8][4];
#pragma unroll
    for (int mi = 0; mi < 2; mi++)
#pragma unroll
        for (int ni = 0; ni < 8; ni++)
#pragma unroll
            for (int e = 0; e < 4; e++) acc[mi][ni][e] = 0.f;

    const __half* Ag = g_oh + (size_t)(mTile * 128) * 512;
    const __half* Bg = g_wph + (size_t)n0 * 512;
    GEMM_MAIN(Ag, Bg)

#pragma unroll
    for (int ni = 0; ni < 8; ni++) {
        int n  = n0 + warpN * 64 + ni * 8 + 2 * t4;
        float b0 = bias[n], b1 = bias[n + 1];
#pragma unroll
        for (int mi = 0; mi < 2; mi++) {
#pragma unroll
            for (int rr2 = 0; rr2 < 2; rr2++) {
                int m   = mTile * 128 + warpM * 32 + mi * 16 + g + rr2 * 8;
                int win = m >> 6, tt = m & 63;
                int b   = win >> 8;
                int wh  = (win >> 4) & 15;
                int ww  = win & 15;
                int ii  = tt >> 3, jj = tt & 7;
                int rO  = (wh * 8 + ii + 4) & 127;
                int cO  = (ww * 8 + jj + 4) & 127;
                size_t off = ((((size_t)b << 7) | rO) << 7 | cO) << 9;
                float2 v = make_float2(acc[mi][ni][rr2 * 2 + 0] + b0,
                                       acc[mi][ni][rr2 * 2 + 1] + b1);
                *(float2*)(out + off + n) = v;
            }
        }
    }
}

// ---------------------------------------------------------------------------
extern "C" void kernel_launch(void* const* d_in, const int* in_sizes, int n_in,
                              void* d_out, int out_size)
{
    const float* x      = (const float*)d_in[0];
    const float* qkv_w  = (const float*)d_in[1];
    const float* qkv_b  = (const float*)d_in[2];
    const float* proj_w = (const float*)d_in[3];
    const float* proj_b = (const float*)d_in[4];
    float* out = (float*)d_out;

    cudaFuncSetAttribute(k_qkv_gemm,  cudaFuncAttributeMaxDynamicSharedMemorySize, SMEM_BYTES);
    cudaFuncSetAttribute(k_proj_gemm, cudaFuncAttributeMaxDynamicSharedMemorySize, SMEM_BYTES);

    k_prep<<<32768 + 512, 128>>>(x, qkv_w, proj_w);
    k_qkv_gemm<<<dim3(12, 1024), 256, SMEM_BYTES>>>(qkv_b);
    k_attn_f16<<<2048 * 8, 128>>>();
    k_proj_gemm<<<dim3(4, 1024), 256, SMEM_BYTES>>>(proj_b, out);
}

// round 14
// speedup vs baseline: 2.1713x; 1.0923x over previous
#include <cuda_runtime.h>
#include <cuda_fp16.h>
#include <cstdint>

// Problem constants:
// B=8, H=W=128, DIM=512, NH=8, HD=64, WIN=8x8 (N=64 tok/window), SHIFT=(4,4)
// windows: 2048 ; rows M = 131072

// Scratch (device globals = sanctioned scratch)
__device__ __half g_qkvh[3u * 2048u * 8u * 64u * 64u]; // [part][win][h][t][d] fp16; q,k RoPE'd
__device__ __half g_xh [131072u * 512u];               // gathered x, fp16
__device__ __half g_oh [131072u * 512u];               // attention out, fp16
__device__ __half g_wqh[1536u * 512u];                 // qkv_w fp16
__device__ __half g_wph[512u * 512u];                  // proj_w fp16

#define L2T16 0.8304820237218406f      // log2(10000)/16

// ---------------------------------------------------------------------------
// helpers
// ---------------------------------------------------------------------------
__device__ __forceinline__ void cp16(uint32_t smem, const void* gmem) {
    asm volatile("cp.async.cg.shared.global [%0], [%1], 16;\n" :: "r"(smem), "l"(gmem));
}
__device__ __forceinline__ void mma_f16(float* c, const uint32_t* a, const uint32_t* b) {
    asm volatile(
        "mma.sync.aligned.m16n8k16.row.col.f32.f16.f16.f32 "
        "{%0,%1,%2,%3}, {%4,%5,%6,%7}, {%8,%9}, {%0,%1,%2,%3};"
        : "+f"(c[0]), "+f"(c[1]), "+f"(c[2]), "+f"(c[3])
        : "r"(a[0]), "r"(a[1]), "r"(a[2]), "r"(a[3]), "r"(b[0]), "r"(b[1]));
}
__device__ __forceinline__ uint32_t pack_h2(float v0, float v1) {
    uint32_t p;
    asm("cvt.rn.f16x2.f32 %0, %1, %2;" : "=r"(p) : "f"(v1), "f"(v0));
    return p;
}
__device__ __forceinline__ void ldsm_x4(uint32_t* d, uint32_t addr) {
    asm volatile("ldmatrix.sync.aligned.m8n8.x4.shared.b16 {%0,%1,%2,%3}, [%4];"
                 : "=r"(d[0]), "=r"(d[1]), "=r"(d[2]), "=r"(d[3]) : "r"(addr));
}

// GEMM smem geometry (BK=64): rows of 64 halves + 16B pad = 144 bytes.
#define ROWB 144
#define STAGE_B (256 * ROWB)            // A(128 rows) + B(128 rows) = 36864 B
#define SMEM_BYTES (3 * STAGE_B)        // 110592 B -> 2 CTAs/SM

// ---------------------------------------------------------------------------
// Kernel 0: prep — gather x (roll+partition) -> g_xh (fp16); weights -> fp16.
// 4 rows per CTA, 128 threads, fully coalesced.
// ---------------------------------------------------------------------------
__global__ __launch_bounds__(128) void k_prep(const float* __restrict__ x,
                                              const float* __restrict__ qkv_w,
                                              const float* __restrict__ proj_w)
{
    const int bid = blockIdx.x;
    const int tid = threadIdx.x;

#pragma unroll
    for (int it = 0; it < 4; it++) {
        int e   = tid + it * 128;       // 0..511
        int rl  = e >> 7;               // row within CTA group (0..3)
        int f4  = e & 127;              // float4 index within row

        const float* src;
        __half* dst;
        if (bid < 32768) {
            int m   = bid * 4 + rl;
            int win = m >> 6, t = m & 63;
            int b   = win >> 8;
            int wh  = (win >> 4) & 15;
            int ww  = win & 15;
            int i   = t >> 3, j = t & 7;
            int r   = (wh * 8 + i + 4) & 127;     // roll(-4) gather
            int c   = (ww * 8 + j + 4) & 127;
            src = x + ((size_t)((((b << 7) | r) << 7) | c) << 9);
            dst = g_xh + (size_t)m * 512;
        } else {
            int w = (bid - 32768) * 4 + rl;        // 0..2047
            if (w < 1536) { src = qkv_w + (size_t)w * 512;           dst = g_wqh + (size_t)w * 512; }
            else          { src = proj_w + (size_t)(w - 1536) * 512; dst = g_wph + (size_t)(w - 1536) * 512; }
        }

        float4 v = ((const float4*)src)[f4];
        uint2 o;
        o.x = pack_h2(v.x, v.y);
        o.y = pack_h2(v.z, v.w);
        ((uint2*)dst)[f4] = o;
    }
}

// ---------------------------------------------------------------------------
// fp16 GEMM core: BM=BN=128, BK=64, K=512 (8 ktiles, FULLY UNROLLED),
// 256 threads, 8 warps (4M x 2N), warp tile 32x64, m16n8k16,
// all-x4 ldmatrix fragments, 3-stage cp.async, 1 barrier per ktile.
// ---------------------------------------------------------------------------
#define GEMM_MAIN(APTR, BPTR)                                                  \
    const int q_  = lane >> 3, r_ = lane & 7;                                  \
    uint32_t aLane[2];                                                         \
    _Pragma("unroll")                                                          \
    for (int mi = 0; mi < 2; mi++)                                             \
        aLane[mi] = (uint32_t)((warpM * 32 + mi * 16 + (q_ & 1) * 8 + r_) * ROWB \
                               + (q_ >> 1) * 16);                              \
    const uint32_t bLane = (uint32_t)(128 * ROWB +                             \
        (warpN * 64 + ((lane >> 4) << 3) + r_) * ROWB + ((q_ & 1) * 16));      \
    auto loadStage = [&](int s, int k0) {                                      \
        uint32_t ab = smemBase + s * STAGE_B;                                  \
        uint32_t bb = ab + 128 * ROWB;                                         \
        _Pragma("unroll")                                                      \
        for (int it = 0; it < 4; it++) {                                       \
            int ch = tid + it * 256;          /* 0..1023 */                    \
            int row = ch >> 3, ci = ch & 7;                                    \
            cp16(ab + row * ROWB + ci * 16, APTR + (size_t)row * 512 + k0 + ci * 8); \
            cp16(bb + row * ROWB + ci * 16, BPTR + (size_t)row * 512 + k0 + ci * 8); \
        }                                                                      \
    };                                                                         \
    loadStage(0, 0);                                                           \
    asm volatile("cp.async.commit_group;\n");                                  \
    loadStage(1, 64);                                                          \
    asm volatile("cp.async.commit_group;\n");                                  \
    asm volatile("cp.async.wait_group 1;\n");                                  \
    __syncthreads();                                                           \
    _Pragma("unroll")                                                          \
    for (int kt = 0; kt < 8; kt++) {                                           \
        if (kt + 2 < 8) {                                                      \
            loadStage((kt + 2) % 3, (kt + 2) * 64);                            \
            asm volatile("cp.async.commit_group;\n");                          \
        }                                                                      \
        const uint32_t stA = smemBase + (kt % 3) * STAGE_B;                    \
        _Pragma("unroll")                                                      \
        for (int ks = 0; ks < 4; ks++) {                                       \
            uint32_t af[2][4];                                                 \
            ldsm_x4(af[0], stA + aLane[0] + ks * 32);                          \
            ldsm_x4(af[1], stA + aLane[1] + ks * 32);                          \
            _Pragma("unroll")                                                  \
            for (int ni2 = 0; ni2 < 4; ni2++) {                                \
                uint32_t bf[4];                                                \
                ldsm_x4(bf, stA + bLane + ni2 * (16 * ROWB) + ks * 32);        \
                mma_f16(acc[0][ni2 * 2 + 0], af[0], bf);                       \
                mma_f16(acc[1][ni2 * 2 + 0], af[1], bf);                       \
                mma_f16(acc[0][ni2 * 2 + 1], af[0], bf + 2);                   \
                mma_f16(acc[1][ni2 * 2 + 1], af[1], bf + 2);                   \
            }                                                                  \
        }                                                                      \
        if (kt < 7) {                                                          \
            if (kt + 2 < 8) asm volatile("cp.async.wait_group 1;\n");          \
            else            asm volatile("cp.async.wait_group 0;\n");          \
            __syncthreads();                                                   \
        }                                                                      \
    }

// ---------------------------------------------------------------------------
// Kernel 1: QKV GEMM (fp16) + bias + fused RoPE/scale + fp16 pack -> g_qkvh.
//   M=131072 K=512 N=1536
// ---------------------------------------------------------------------------
__global__ __launch_bounds__(256, 2) void k_qkv_gemm(const float* __restrict__ bias)
{
    extern __shared__ uint32_t sm32[];
    const uint32_t smemBase = (uint32_t)__cvta_generic_to_shared(sm32);

    const int tid   = threadIdx.x;
    const int nTile = blockIdx.x;
    const int mTile = blockIdx.y;

    const int warpId = tid >> 5, lane = tid & 31;
    const int warpM  = warpId & 3;
    const int warpN  = warpId >> 2;
    const int n0     = nTile * 128;
    const int g      = lane >> 2, t4 = lane & 3;

    float acc[2][8][4];
#pragma unroll
    for (int mi = 0; mi < 2; mi++)
#pragma unroll
        for (int ni = 0; ni < 8; ni++)
#pragma unroll
            for (int e = 0; e < 4; e++) acc[mi][ni][e] = 0.f;

    const __half* Ag = g_xh + (size_t)(mTile * 128) * 512;
    const __half* Bg = g_wqh + (size_t)n0 * 512;
    GEMM_MAIN(Ag, Bg)

    const int nbase = n0 + warpN * 64;     // 64-aligned -> one (part, head)
    const int part  = nbase >> 9;
    const int h     = (nbase >> 6) & 7;

    // bias (reference: GEMM + b, THEN rope)
#pragma unroll
    for (int ni = 0; ni < 8; ni++) {
        int n = nbase + ni * 8 + 2 * t4;
        float b0 = bias[n], b1 = bias[n + 1];
#pragma unroll
        for (int mi = 0; mi < 2; mi++) {
            acc[mi][ni][0] += b0; acc[mi][ni][1] += b1;
            acc[mi][ni][2] += b0; acc[mi][ni][3] += b1;
        }
    }

    if (part < 2) {
        const float scale = (part == 0) ? 0.125f : 1.0f;
        float invv[2][2];  // [ni&1][j]: e = (ni&1)*8 + 2*t4 + j
#pragma unroll
        for (int p = 0; p < 2; p++)
#pragma unroll
            for (int j = 0; j < 2; j++)
                invv[p][j] = exp2f(-(float)(p * 8 + 2 * t4 + j) * L2T16);

#pragma unroll
        for (int mi = 0; mi < 2; mi++) {
#pragma unroll
            for (int rr = 0; rr < 2; rr++) {
                int t = (mTile * 128 + warpM * 32 + mi * 16 + g + rr * 8) & 63;
                float posR = (float)(t >> 3), posC = (float)(t & 7);
#pragma unroll
                for (int qq = 0; qq < 4; qq++) {
                    const int niList[4] = {0, 1, 4, 5};
                    int ni = niList[qq];
                    float pos = (ni < 4) ? posR : posC;
#pragma unroll
                    for (int j = 0; j < 2; j++) {
                        float ang = pos * invv[ni & 1][j];
                        float sv, cv;
                        __sincosf(ang, &sv, &cv);
                        float a = acc[mi][ni][rr * 2 + j];
                        float b = acc[mi][ni + 2][rr * 2 + j];
                        acc[mi][ni][rr * 2 + j]     = (a * cv - b * sv) * scale;
                        acc[mi][ni + 2][rr * 2 + j] = (b * cv + a * sv) * scale;
                    }
                }
            }
        }
    }

    // pack fp16 + scatter into g_qkvh[part][win][h][t][d]
    uint32_t* gq = (uint32_t*)g_qkvh;
#pragma unroll
    for (int ni = 0; ni < 8; ni++) {
        int d0 = ni * 8 + 2 * t4;          // even
#pragma unroll
        for (int mi = 0; mi < 2; mi++) {
#pragma unroll
            for (int rr = 0; rr < 2; rr++) {
                int m   = mTile * 128 + warpM * 32 + mi * 16 + g + rr * 8;
                int win = m >> 6, t = m & 63;
                size_t idx = ((((size_t)part * 2048 + win) * 8 + h) * 64 + t) * 64 + d0;
                gq[idx >> 1] = pack_h2(acc[mi][ni][rr * 2 + 0], acc[mi][ni][rr * 2 + 1]);
            }
        }
    }
}

// ---------------------------------------------------------------------------
// Kernel 2: per (window, head) attention, all-fp16 MMA (fp32 accum/softmax).
// V transpose into smem uses an XOR chunk swizzle (t>>3 ^ (d>>3)) to kill the
// 16-way STS bank conflicts of the naive [d][t] store. PV fragment reads are
// adjusted to the swizzled chunk index (still conflict-free).
// ---------------------------------------------------------------------------
#define ASTW 36   // words per 64-half row (32 data + 4 pad)

__global__ __launch_bounds__(128) void k_attn_f16()
{
    __shared__ uint32_t Qs[64 * ASTW];   // Q [t][d]; P overlays own strip
    __shared__ uint32_t Ks[64 * ASTW];   // K [t][d]
    __shared__ uint32_t Vs[64 * ASTW];   // V [d][t], chunk-swizzled

    const int tid  = threadIdx.x;
    const int warp = tid >> 5;
    const int lane = tid & 31;
    const int g    = lane >> 2;
    const int c    = lane & 3;
    const int m0   = warp * 16;

    const int win = blockIdx.x >> 3;
    const int h   = blockIdx.x & 7;

    const size_t qoff = ((size_t)win * 8 + h) * 4096;
    const size_t pstr = (size_t)2048 * 8 * 4096;
    const uint4* qg = (const uint4*)(g_qkvh + qoff);
    const uint4* kg = (const uint4*)(g_qkvh + pstr + qoff);
    const uint4* vg = (const uint4*)(g_qkvh + 2 * pstr + qoff);
    __half* VsH = (__half*)Vs;

#pragma unroll
    for (int it = 0; it < 4; it++) {
        int e4 = tid + it * 128;
        int t  = e4 >> 3;
        int ci = e4 & 7;
        *(uint4*)(Qs + t * ASTW + ci * 4) = qg[e4];
        *(uint4*)(Ks + t * ASTW + ci * 4) = kg[e4];
        uint4 w = vg[e4];
        const __half* hb = (const __half*)&w;
        // V transpose with chunk swizzle: half (d=col, t) stored at
        // col*72 + ((t>>3)^((col>>3)&7))*8 + (t&7)
        int tc = (t >> 3), tl = (t & 7);
#pragma unroll
        for (int k = 0; k < 8; k++) {
            int col = ci * 8 + k;
            VsH[col * (2 * ASTW) + (((tc ^ (col >> 3)) & 7) << 3) + tl] = hb[k];
        }
    }
    __syncthreads();

    uint32_t areg[4][4];
#pragma unroll
    for (int ks = 0; ks < 4; ks++) {
        const uint32_t* ap = Qs + (m0 + g) * ASTW + ks * 8 + c;
        areg[ks][0] = ap[0];
        areg[ks][1] = ap[8 * ASTW];
        areg[ks][2] = ap[4];
        areg[ks][3] = ap[8 * ASTW + 4];
    }

    float sacc[8][4];
#pragma unroll
    for (int ni = 0; ni < 8; ni++)
#pragma unroll
        for (int e = 0; e < 4; e++) sacc[ni][e] = 0.f;

#pragma unroll
    for (int ni = 0; ni < 8; ni++) {
        const uint32_t* bb = Ks + (ni * 8 + g) * ASTW + c;
#pragma unroll
        for (int ks = 0; ks < 4; ks++) {
            uint32_t bf[2] = { bb[ks * 8], bb[ks * 8 + 4] };
            mma_f16(sacc[ni], areg[ks], bf);
        }
    }

    const bool maskOn = (((win >> 4) & 15) == 15);
    const bool warpLo = (warp < 2);

    float mx1 = -1e30f, mx2 = -1e30f;
#pragma unroll
    for (int ni = 0; ni < 8; ni++) {
        float msub = (maskOn && ((ni < 4) != warpLo)) ? 100.f : 0.f;
        sacc[ni][0] -= msub; sacc[ni][1] -= msub;
        sacc[ni][2] -= msub; sacc[ni][3] -= msub;
        mx1 = fmaxf(mx1, fmaxf(sacc[ni][0], sacc[ni][1]));
        mx2 = fmaxf(mx2, fmaxf(sacc[ni][2], sacc[ni][3]));
    }
    mx1 = fmaxf(mx1, __shfl_xor_sync(0xffffffffu, mx1, 1));
    mx1 = fmaxf(mx1, __shfl_xor_sync(0xffffffffu, mx1, 2));
    mx2 = fmaxf(mx2, __shfl_xor_sync(0xffffffffu, mx2, 1));
    mx2 = fmaxf(mx2, __shfl_xor_sync(0xffffffffu, mx2, 2));

    float s1 = 0.f, s2 = 0.f;
#pragma unroll
    for (int ni = 0; ni < 8; ni++) {
        sacc[ni][0] = __expf(sacc[ni][0] - mx1);
        sacc[ni][1] = __expf(sacc[ni][1] - mx1);
        sacc[ni][2] = __expf(sacc[ni][2] - mx2);
        sacc[ni][3] = __expf(sacc[ni][3] - mx2);
        s1 += sacc[ni][0] + sacc[ni][1];
        s2 += sacc[ni][2] + sacc[ni][3];
    }
    s1 += __shfl_xor_sync(0xffffffffu, s1, 1);
    s1 += __shfl_xor_sync(0xffffffffu, s1, 2);
    s2 += __shfl_xor_sync(0xffffffffu, s2, 1);
    s2 += __shfl_xor_sync(0xffffffffu, s2, 2);
    const float i1 = 1.f / s1, i2 = 1.f / s2;

#pragma unroll
    for (int ni = 0; ni < 8; ni++) {
        Qs[(m0 + g) * ASTW + ni * 4 + c]     = pack_h2(sacc[ni][0] * i1, sacc[ni][1] * i1);
        Qs[(m0 + g + 8) * ASTW + ni * 4 + c] = pack_h2(sacc[ni][2] * i2, sacc[ni][3] * i2);
    }
    __syncwarp();

    uint32_t preg[4][4];
#pragma unroll
    for (int ks = 0; ks < 4; ks++) {
        const uint32_t* pp = Qs + (m0 + g) * ASTW + ks * 8 + c;
        preg[ks][0] = pp[0];
        preg[ks][1] = pp[8 * ASTW];
        preg[ks][2] = pp[4];
        preg[ks][3] = pp[8 * ASTW + 4];
    }

    float oacc[8][4];
#pragma unroll
    for (int ni = 0; ni < 8; ni++)
#pragma unroll
        for (int e = 0; e < 4; e++) oacc[ni][e] = 0.f;

#pragma unroll
    for (int ni = 0; ni < 8; ni++) {
        const uint32_t* rowp = Vs + (ni * 8 + g) * ASTW;
#pragma unroll
        for (int ks = 0; ks < 4; ks++) {
            // swizzled chunk indices: t-chunks (2ks) and (2ks+1), XOR ni
            uint32_t bf[2];
            bf[0] = rowp[((((2 * ks)     ^ ni) & 7) << 2) + c];
            bf[1] = rowp[((((2 * ks + 1) ^ ni) & 7) << 2) + c];
            mma_f16(oacc[ni], preg[ks], bf);
        }
    }

    uint32_t* goh = (uint32_t*)g_oh;
    const size_t mrow1 = (size_t)win * 64 + m0 + g;
    const size_t mrow2 = mrow1 + 8;
#pragma unroll
    for (int ni = 0; ni < 8; ni++) {
        int d0 = h * 64 + ni * 8 + 2 * c;
        goh[(mrow1 * 512 + d0) >> 1] = pack_h2(oacc[ni][0], oacc[ni][1]);
        goh[(mrow2 * 512 + d0) >> 1] = pack_h2(oacc[ni][2], oacc[ni][3]);
    }
}

// ---------------------------------------------------------------------------
// Kernel 3: proj GEMM (fp16) + bias + unpartition/roll scatter.
//   M=131072 K=512 N=512
// ---------------------------------------------------------------------------
__global__ __launch_bounds__(256, 2) void k_proj_gemm(const float* __restrict__ bias,
                                                      float* __restrict__ out)
{
    extern __shared__ uint32_t sm32[];
    const uint32_t smemBase = (uint32_t)__cvta_generic_to_shared(sm32);

    const int tid   = threadIdx.x;
    const int nTile = blockIdx.x;
    const int mTile = blockIdx.y;

    const int warpId = tid >> 5, lane = tid & 31;
    const int warpM  = warpId & 3;
    const int warpN  = warpId >> 2;
    const int n0     = nTile * 128;
    const int g      = lane >> 2, t4 = lane & 3;

    float acc[2][8][4];
#pragma unroll
    for (int mi = 0; mi < 2; mi++)
#pragma unroll
        for (int ni = 0; ni < 8; ni++)
#pragma unroll
            for (int e = 0; e < 4; e++) acc[mi][ni][e] = 0.f;

    const __half* Ag = g_oh + (size_t)(mTile * 128) * 512;
    const __half* Bg = g_wph + (size_t)n0 * 512;
    GEMM_MAIN(Ag, Bg)

#pragma unroll
    for (int ni = 0; ni < 8; ni++) {
        int n  = n0 + warpN * 64 + ni * 8 + 2 * t4;
        float b0 = bias[n], b1 = bias[n + 1];
#pragma unroll
        for (int mi = 0; mi < 2; mi++) {
#pragma unroll
            for (int rr2 = 0; rr2 < 2; rr2++) {
                int m   = mTile * 128 + warpM * 32 + mi * 16 + g + rr2 * 8;
                int win = m >> 6, tt = m & 63;
                int b   = win >> 8;
                int wh  = (win >> 4) & 15;
                int ww  = win & 15;
                int ii  = tt >> 3, jj = tt & 7;
                int rO  = (wh * 8 + ii + 4) & 127;
                int cO  = (ww * 8 + jj + 4) & 127;
                size_t off = ((((size_t)b << 7) | rO) << 7 | cO) << 9;
                float2 v = make_float2(acc[mi][ni][rr2 * 2 + 0] + b0,
                                       acc[mi][ni][rr2 * 2 + 1] + b1);
                *(float2*)(out + off + n) = v;
            }
        }
    }
}

// ---------------------------------------------------------------------------
extern "C" void kernel_launch(void* const* d_in, const int* in_sizes, int n_in,
                              void* d_out, int out_size)
{
    const float* x      = (const float*)d_in[0];
    const float* qkv_w  = (const float*)d_in[1];
    const float* qkv_b  = (const float*)d_in[2];
    const float* proj_w = (const float*)d_in[3];
    const float* proj_b = (const float*)d_in[4];
    float* out = (float*)d_out;

    cudaFuncSetAttribute(k_qkv_gemm,  cudaFuncAttributeMaxDynamicSharedMemorySize, SMEM_BYTES);
    cudaFuncSetAttribute(k_proj_gemm, cudaFuncAttributeMaxDynamicSharedMemorySize, SMEM_BYTES);

    k_prep<<<32768 + 512, 128>>>(x, qkv_w, proj_w);
    k_qkv_gemm<<<dim3(12, 1024), 256, SMEM_BYTES>>>(qkv_b);
    k_attn_f16<<<2048 * 8, 128>>>();
    k_proj_gemm<<<dim3(4, 1024), 256, SMEM_BYTES>>>(proj_b, out);
}